// round 13
// baseline (speedup 1.0000x reference)
#include <cuda_runtime.h>
#include <cuda_fp16.h>
#include <cstdint>

// Problem dims
#define B_   32
#define T_   50
#define N_   100
#define D_   4
#define E_   9900          // N*(N-1)
#define BE_  316800        // B*E
#define H_   256           // hidden
#define NIN_ 200           // T*D

// Scratch (device globals; no allocation allowed)
__device__ float  g_xskip[BE_ * H_ / 2];   // __half x_skip buffer (162 MB)
__device__ float  g_nodeA[B_ * N_ * H_];   // 3.3 MB
__device__ float  g_nodeB[B_ * N_ * H_];   // 3.3 MB
__device__ float  g_pq   [B_ * N_ * 512];  // P|Q node projections, 6.6 MB
__device__ __half g_wth  [768 * 256];      // frag-ordered fp16 weights: w2b|w4c|w4b

enum { MODE_DIR = 0, MODE_X = 1 };

typedef unsigned long long u64;

// ---------------- small PTX helpers ----------------
__device__ __forceinline__ uint32_t smem_to_u32(const void* p) {
    uint32_t a;
    asm("{ .reg .u64 t; cvta.to.shared.u64 t, %1; cvt.u32.u64 %0, t; }" : "=r"(a) : "l"(p));
    return a;
}
__device__ __forceinline__ uint32_t pkh2(float x, float y) {
    __half2 h = __floats2half2_rn(x, y);
    return *(uint32_t*)&h;
}
__device__ __forceinline__ void cp16(uint32_t s, const void* g) {
    asm volatile("cp.async.cg.shared.global [%0], [%1], 16;" :: "r"(s), "l"(g) : "memory");
}
__device__ __forceinline__ void cp_commit() { asm volatile("cp.async.commit_group;" ::: "memory"); }
__device__ __forceinline__ void cp_wait0()  { asm volatile("cp.async.wait_group 0;" ::: "memory"); }

__device__ __forceinline__ void mma_f16(float* c, const uint32_t* a, uint32_t b0, uint32_t b1) {
    asm volatile(
        "mma.sync.aligned.m16n8k16.row.col.f32.f16.f16.f32 "
        "{%0,%1,%2,%3}, {%4,%5,%6,%7}, {%8,%9}, {%0,%1,%2,%3};"
        : "+f"(c[0]), "+f"(c[1]), "+f"(c[2]), "+f"(c[3])
        : "r"(a[0]), "r"(a[1]), "r"(a[2]), "r"(a[3]), "r"(b0), "r"(b1));
}

// edge index helpers
__device__ __forceinline__ void edge_nodes(int m, int& bn_rcv, int& bn_snd) {
    int b = m / E_, e = m - b * E_;
    int rcv = e / (N_ - 1), jj = e - rcv * (N_ - 1);
    int snd = jj + (jj >= rcv ? 1 : 0);
    bn_rcv = b * N_ + rcv;
    bn_snd = b * N_ + snd;
}

// SIMT f32x2 primitives
__device__ __forceinline__ u64 pk2(float lo, float hi) {
    u64 r; asm("mov.b64 %0, {%1, %2};" : "=l"(r) : "f"(lo), "f"(hi)); return r;
}
__device__ __forceinline__ void fma2(u64& d, u64 a, u64 b) {
    asm("fma.rn.f32x2 %0, %1, %2, %0;" : "+l"(d) : "l"(a), "l"(b));
}
__device__ __forceinline__ void unpk2(float& lo, float& hi, u64 v) {
    asm("mov.b64 {%0, %1}, %2;" : "=f"(lo), "=f"(hi) : "l"(v));
}

// ---------------- zero kernel for node accumulator ----------------
__global__ void zero_k(float* __restrict__ p, int n)
{
    const int i = blockIdx.x * 1024 + threadIdx.x * 4;
    if (i < n) *(float4*)(p + i) = make_float4(0.f, 0.f, 0.f, 0.f);
}

// ==================== fused2: x_skip = relu(P[recv]+Q[send]) @ W2 + b2 ====================
// Also accumulates the edge->node mean into V (nodeA) via atomics.
// 256 threads = 8 warps (4m x 2n), warp tile 32x128.
// smem: hidden 128 x 132 b32 (67584 B) at 0; B[2] 16 KB each. total 100352 B.
#define F2_SMB(p) (67584u + (p) * 16384u)
#define F2_BYTES  100352

__global__ __launch_bounds__(256, 1)
void fused2(const float* __restrict__ PQ, const __half* __restrict__ W2,
            const float* __restrict__ b2v, __half* __restrict__ C,
            float* __restrict__ V)
{
    extern __shared__ char smem[];
    const uint32_t sbase = smem_to_u32(smem);
    const int tid = threadIdx.x;
    const int m0 = blockIdx.x * 128;

    auto stageB = [&](int t, int p) {
        const char* hs = (const char*)(W2 + (size_t)t * 8192);
        const uint32_t dh = sbase + F2_SMB(p);
#pragma unroll
        for (int i = 0; i < 4; ++i) {
            const int e4 = i * 256 + tid;
            cp16(dh + e4 * 16, hs + e4 * 16);
        }
    };

    stageB(0, 0);
    cp_commit();

    // ---- gather-add: hidden = relu(P[recv] + Q[send]) (bias pre-folded into P) ----
    {
        const int arow = tid >> 1, side = tid & 1;
        int bnr, bns; edge_nodes(m0 + arow, bnr, bns);
        const float4* Pr = (const float4*)(PQ + (size_t)bnr * 512 + side * 128);
        const float4* Qr = (const float4*)(PQ + (size_t)bns * 512 + 256 + side * 128);
        uint32_t* dst = (uint32_t*)smem + arow * 132 + side * 64;
#pragma unroll 8
        for (int j = 0; j < 32; ++j) {
            const float4 p = Pr[j], q = Qr[j];
            const float v0 = fmaxf(p.x + q.x, 0.f), v1 = fmaxf(p.y + q.y, 0.f);
            const float v2 = fmaxf(p.z + q.z, 0.f), v3 = fmaxf(p.w + q.w, 0.f);
            dst[2 * j]     = pkh2(v0, v1);
            dst[2 * j + 1] = pkh2(v2, v3);
        }
    }
    cp_wait0();
    __syncthreads();

    // ---- GEMM2: hidden[128,256] @ W2 ----
    const int wid = tid >> 5, lane = tid & 31;
    const int warp_m = wid >> 1, warp_n = wid & 1;
    const int g = lane >> 2, t4 = lane & 3;

    float acc[2][16][4];
#pragma unroll
    for (int i = 0; i < 2; i++)
#pragma unroll
        for (int j = 0; j < 16; j++)
#pragma unroll
            for (int c = 0; c < 4; c++) acc[i][j][c] = 0.f;

#pragma unroll 1
    for (int t2 = 0; t2 < 8; ++t2) {
        const int p = t2 & 1;
        if (t2 + 1 < 8) { stageB(t2 + 1, p ^ 1); cp_commit(); }
        {
            const uint32_t* sH = (const uint32_t*)smem;
            const uint2*    sB = (const uint2*)(smem + F2_SMB(p));
#pragma unroll
            for (int kk = 0; kk < 2; ++kk) {
                uint32_t a[2][4];
#pragma unroll
                for (int mt = 0; mt < 2; ++mt) {
                    const int r0 = warp_m * 32 + mt * 16 + g;
                    const int cb = t2 * 16 + kk * 8 + t4;
                    a[mt][0] = sH[r0 * 132 + cb];
                    a[mt][1] = sH[(r0 + 8) * 132 + cb];
                    a[mt][2] = sH[r0 * 132 + cb + 4];
                    a[mt][3] = sH[(r0 + 8) * 132 + cb + 4];
                }
#pragma unroll
                for (int nt = 0; nt < 16; ++nt) {
                    const int bi = warp_n * 1024 + ((nt * 2 + kk) * 32 + lane);
                    uint2 b = sB[bi];
#pragma unroll
                    for (int mt = 0; mt < 2; ++mt)
                        mma_f16(acc[mt][nt], a[mt], b.x, b.y);
                }
            }
        }
        cp_wait0();
        __syncthreads();
    }

    // epilogue: bias, fp16 store to gmem + smem (for aggregation)
    {
        uint32_t* sX = (uint32_t*)smem;    // hidden region dead; stride 132
#pragma unroll
        for (int mt = 0; mt < 2; ++mt) {
#pragma unroll
            for (int nt = 0; nt < 16; ++nt) {
                const int rl = warp_m * 32 + mt * 16 + g;
                const int col = warp_n * 128 + nt * 8 + t4 * 2;
                const float2 bb = *(const float2*)(b2v + col);
                const uint32_t h0 = pkh2(acc[mt][nt][0] + bb.x, acc[mt][nt][1] + bb.y);
                const uint32_t h1 = pkh2(acc[mt][nt][2] + bb.x, acc[mt][nt][3] + bb.y);
                *(uint32_t*)(C + (size_t)(m0 + rl) * 256 + col)     = h0;
                *(uint32_t*)(C + (size_t)(m0 + rl + 8) * 256 + col) = h1;
                sX[rl * 132 + (col >> 1)]       = h0;
                sX[(rl + 8) * 132 + (col >> 1)] = h1;
            }
        }
    }
    __syncthreads();

    // ---- aggregation: per node segment (bn = m/99, contiguous), sum/100, atomicAdd ----
    {
        const uint32_t* sX = (const uint32_t*)smem;
        const int cp  = tid & 127;      // column pair
        const int par = tid >> 7;       // segment parity
        const int bn0 = m0 / (N_ - 1);
        const int bn1 = (m0 + 127) / (N_ - 1);
        for (int bn = bn0 + par; bn <= bn1; bn += 2) {
            const int lo = max(bn * (N_ - 1) - m0, 0);
            const int hi = min(bn * (N_ - 1) + (N_ - 1) - m0, 128);
            float s0 = 0.f, s1 = 0.f;
            for (int r = lo; r < hi; ++r) {
                const uint32_t hv = sX[r * 132 + cp];
                __half2 h = *(const __half2*)&hv;
                float2 f = __half22float2(h);
                s0 += f.x; s1 += f.y;
            }
            atomicAdd(&V[(size_t)bn * 256 + cp * 2],     s0 * (1.0f / N_));
            atomicAdd(&V[(size_t)bn * 256 + cp * 2 + 1], s1 * (1.0f / N_));
        }
    }
}

// ==================== fused4 + output head ====================
// out[M,4] = (relu(xs@W1 + P4[recv]+Q4[send]) @ W2 + b2) @ wo + bo
#define F4_SMA(p) ((p) * 10240u)
#define F4_SMH    (20480u)
#define F4_SMB(p) (88064u + (p) * 16384u)
#define F4_BYTES  120832

__global__ __launch_bounds__(256, 1)
void fused4(const __half* __restrict__ XS, const float* __restrict__ PQ,
            const __half* __restrict__ W1, const __half* __restrict__ W2,
            const float* __restrict__ b2v, const float* __restrict__ wo,
            const float* __restrict__ bo, float* __restrict__ out)
{
    extern __shared__ char smem[];
    const uint32_t sbase = smem_to_u32(smem);
    const int tid = threadIdx.x;
    const int m0 = blockIdx.x * 128;

    const int arow = tid >> 1;
    const int kh   = (tid & 1) << 4;
    const __half* xrow = XS + (size_t)(m0 + arow) * 256;

    auto stageA = [&](int t, int p) {
        const uint32_t dst = sbase + F4_SMA(p) + (arow * 20 + (tid & 1) * 8) * 4;
        const char* src = (const char*)(xrow + t * 32 + kh);
        cp16(dst, src);
        cp16(dst + 16, src + 16);
    };
    auto stageB = [&](const __half* W, int t, int p) {
        const char* hs = (const char*)(W + (size_t)t * 8192);
        const uint32_t dh = sbase + F4_SMB(p);
#pragma unroll
        for (int i = 0; i < 4; ++i) {
            const int e4 = i * 256 + tid;
            cp16(dh + e4 * 16, hs + e4 * 16);
        }
    };

    const int wid = tid >> 5, lane = tid & 31;
    const int warp_m = wid >> 1, warp_n = wid & 1;
    const int g = lane >> 2, t4 = lane & 3;

    float acc[2][16][4];
#pragma unroll
    for (int i = 0; i < 2; i++)
#pragma unroll
        for (int j = 0; j < 16; j++)
#pragma unroll
            for (int c = 0; c < 4; c++) acc[i][j][c] = 0.f;

    // ---- GEMM1: xs[128,256] @ W1 ----
    stageA(0, 0); stageB(W1, 0, 0);
    cp_commit();
    cp_wait0();
    __syncthreads();

#pragma unroll 1
    for (int t = 0; t < 8; ++t) {
        const int p = t & 1;
        if (t + 1 < 8) { stageA(t + 1, p ^ 1); stageB(W1, t + 1, p ^ 1); cp_commit(); }
        {
            const uint32_t* sA = (const uint32_t*)(smem + F4_SMA(p));
            const uint2*    sB = (const uint2*)(smem + F4_SMB(p));
#pragma unroll
            for (int kk = 0; kk < 2; ++kk) {
                uint32_t a[2][4];
#pragma unroll
                for (int mt = 0; mt < 2; ++mt) {
                    const int base = ((warp_m * 2 + mt) * 16 + g) * 20 + kk * 8 + t4;
                    a[mt][0] = sA[base];
                    a[mt][1] = sA[base + 8 * 20];
                    a[mt][2] = sA[base + 4];
                    a[mt][3] = sA[base + 8 * 20 + 4];
                }
#pragma unroll
                for (int nt = 0; nt < 16; ++nt) {
                    const int bi = warp_n * 1024 + ((nt * 2 + kk) * 32 + lane);
                    uint2 b = sB[bi];
#pragma unroll
                    for (int mt = 0; mt < 2; ++mt)
                        mma_f16(acc[mt][nt], a[mt], b.x, b.y);
                }
            }
        }
        cp_wait0();
        __syncthreads();
    }

    // prefetch GEMM2 B tile 0 while doing epilogue 1
    stageB(W2, 0, 0);
    cp_commit();

    // ---- epilogue 1: hidden = relu(acc + P4[recv] + Q4[send]) (b4a folded into P4) ----
    {
        uint32_t* sH = (uint32_t*)(smem + F4_SMH);
#pragma unroll
        for (int mt = 0; mt < 2; ++mt) {
#pragma unroll
            for (int rr = 0; rr < 2; ++rr) {
                const int rloc = warp_m * 32 + mt * 16 + g + rr * 8;
                int bnr, bns; edge_nodes(m0 + rloc, bnr, bns);
                const float* Pr = PQ + (size_t)bnr * 512;
                const float* Qr = PQ + (size_t)bns * 512 + 256;
#pragma unroll
                for (int nt = 0; nt < 16; ++nt) {
                    const int col = warp_n * 128 + nt * 8 + t4 * 2;
                    const float2 p = *(const float2*)(Pr + col);
                    const float2 q = *(const float2*)(Qr + col);
                    const float v0 = fmaxf(acc[mt][nt][rr * 2 + 0] + p.x + q.x, 0.f);
                    const float v1 = fmaxf(acc[mt][nt][rr * 2 + 1] + p.y + q.y, 0.f);
                    sH[rloc * 132 + warp_n * 64 + nt * 4 + t4] = pkh2(v0, v1);
                }
            }
        }
    }
#pragma unroll
    for (int i = 0; i < 2; i++)
#pragma unroll
        for (int j = 0; j < 16; j++)
#pragma unroll
            for (int c = 0; c < 4; c++) acc[i][j][c] = 0.f;

    cp_wait0();
    __syncthreads();

    // ---- GEMM2: hidden @ W2 ----
#pragma unroll 1
    for (int t2 = 0; t2 < 8; ++t2) {
        const int p = t2 & 1;
        if (t2 + 1 < 8) { stageB(W2, t2 + 1, p ^ 1); cp_commit(); }
        {
            const uint32_t* sH = (const uint32_t*)(smem + F4_SMH);
            const uint2*    sB = (const uint2*)(smem + F4_SMB(p));
#pragma unroll
            for (int kk = 0; kk < 2; ++kk) {
                uint32_t a[2][4];
#pragma unroll
                for (int mt = 0; mt < 2; ++mt) {
                    const int r0 = warp_m * 32 + mt * 16 + g;
                    const int cb = t2 * 16 + kk * 8 + t4;
                    a[mt][0] = sH[r0 * 132 + cb];
                    a[mt][1] = sH[(r0 + 8) * 132 + cb];
                    a[mt][2] = sH[r0 * 132 + cb + 4];
                    a[mt][3] = sH[(r0 + 8) * 132 + cb + 4];
                }
#pragma unroll
                for (int nt = 0; nt < 16; ++nt) {
                    const int bi = warp_n * 1024 + ((nt * 2 + kk) * 32 + lane);
                    uint2 b = sB[bi];
#pragma unroll
                    for (int mt = 0; mt < 2; ++mt)
                        mma_f16(acc[mt][nt], a[mt], b.x, b.y);
                }
            }
        }
        cp_wait0();
        __syncthreads();
    }

    // ---- epilogue 2: output head. out = (acc + b4b) @ wo + bo ----
    {
        float p[2][2][4];
#pragma unroll
        for (int mt = 0; mt < 2; ++mt)
#pragma unroll
            for (int rr = 0; rr < 2; ++rr)
#pragma unroll
                for (int j = 0; j < 4; ++j) p[mt][rr][j] = 0.f;

#pragma unroll
        for (int nt = 0; nt < 16; ++nt) {
            const int col = warp_n * 128 + nt * 8 + t4 * 2;
            const float2 bb = *(const float2*)(b2v + col);
            const float4 w0 = *(const float4*)(wo + col * 4);
            const float4 w1 = *(const float4*)(wo + (col + 1) * 4);
#pragma unroll
            for (int mt = 0; mt < 2; ++mt)
#pragma unroll
                for (int rr = 0; rr < 2; ++rr) {
                    const float v0 = acc[mt][nt][rr * 2 + 0] + bb.x;
                    const float v1 = acc[mt][nt][rr * 2 + 1] + bb.y;
                    p[mt][rr][0] += v0 * w0.x + v1 * w1.x;
                    p[mt][rr][1] += v0 * w0.y + v1 * w1.y;
                    p[mt][rr][2] += v0 * w0.z + v1 * w1.z;
                    p[mt][rr][3] += v0 * w0.w + v1 * w1.w;
                }
        }
        // reduce over t4 lanes (lane = g*4 + t4)
#pragma unroll
        for (int mt = 0; mt < 2; ++mt)
#pragma unroll
            for (int rr = 0; rr < 2; ++rr)
#pragma unroll
                for (int j = 0; j < 4; ++j) {
                    float v = p[mt][rr][j];
                    v += __shfl_xor_sync(0xffffffffu, v, 1);
                    v += __shfl_xor_sync(0xffffffffu, v, 2);
                    p[mt][rr][j] = v;
                }
        float* sO = (float*)smem;     // reuse dead A region, 4 KB
        if (t4 == 0) {
#pragma unroll
            for (int mt = 0; mt < 2; ++mt)
#pragma unroll
                for (int rr = 0; rr < 2; ++rr) {
                    const int rloc = warp_m * 32 + mt * 16 + rr * 8 + g;
#pragma unroll
                    for (int j = 0; j < 4; ++j)
                        sO[rloc * 8 + warp_n * 4 + j] = p[mt][rr][j];
                }
        }
        __syncthreads();
#pragma unroll
        for (int it = 0; it < 2; ++it) {
            const int idx = tid + it * 256;
            const int row = idx >> 2, j = idx & 3;
            out[(size_t)(m0 + row) * 4 + j] = sO[row * 8 + j] + sO[row * 8 + 4 + j] + bo[j];
        }
    }
}

// ---------------- merged weight fp16-convert + frag-order scatter (3x K=256) ----------------
__global__ void wsplit3_k(const float* __restrict__ w0, const float* __restrict__ w1s,
                          const float* __restrict__ w2s, __half* __restrict__ oh)
{
    const int grp = blockIdx.x >> 8;                 // 0,1,2
    const int lb  = blockIdx.x & 255;
    const float* w = (grp == 0) ? w0 : (grp == 1) ? w1s : w2s;
    __half* dstb = oh + (size_t)grp * 256 * 256;
    const int idx = lb * 256 + threadIdx.x;          // = k*256 + n
    const int k = idx >> 8, n = idx & 255;
    const __half hv = __float2half_rn(w[idx]);
    const int ny = n >> 7, nr = n & 127;
    const int nt = nr >> 3, gg = nr & 7;
    const int s = k >> 5, kr = k & 31;
    const int kk = kr >> 4, kr16 = kr & 15;
    const int reg = (kr16 >= 8) ? 1 : 0;
    const int t4 = (kr16 & 7) >> 1;
    const int hp = kr16 & 1;
    const int lane = gg * 4 + t4;
    const int dst = (s * 2 + ny) * 4096 + ((nt * 2 + kk) * 32 + lane) * 4 + reg * 2 + hp;
    dstb[dst] = hv;
}

// ---------------- SIMT f32x2 GEMM, 32x64 tiles (node layers, exact fp32) ----------------
template<int MODE, int K, int NOUT, bool RELU>
__global__ __launch_bounds__(256)
void gemm_k32(const float* __restrict__ A, const float* __restrict__ W,
              const float* __restrict__ bias, float* __restrict__ C)
{
    constexpr int TK = 8;
    __shared__ __align__(16) float sA[2][TK][36];
    __shared__ __align__(16) float sB[2][TK][64];

    const int tid = threadIdx.x;
    const int m0 = blockIdx.x * 32, n0 = blockIdx.y * 64;

    // A loader: threads 0..63; B loader: threads 128..255
    const int a_m = (tid & 63) >> 1, a_k = (tid & 1) << 2;
    const int b_k = (tid & 127) >> 4, b_n = (tid & 15) << 2;

    const int m = m0 + a_m;
    const float* pr;
    if (MODE == MODE_DIR) {
        pr = A + (size_t)m * K;
    } else { // MODE_X
        int b = m / N_, n = m - b * N_;
        pr = A + (size_t)b * (T_ * N_ * D_) + (size_t)n * D_;
    }
    auto ldA = [&](int k0) -> float4 {
        const int k = k0 + a_k;
        if (MODE == MODE_DIR) return *(const float4*)(pr + k);
        return *(const float4*)(pr + (size_t)(k >> 2) * (N_ * D_));
    };
    auto ldB = [&](int k0) -> float4 {
        return *(const float4*)(W + (size_t)(k0 + b_k) * NOUT + n0 + b_n);
    };

    const int tx = tid & 15, ty = tid >> 4;   // ty: 16 row-groups of 2, tx: 16 col-groups of 4
    u64 acc[2][2];
#pragma unroll
    for (int i = 0; i < 2; i++) { acc[i][0] = 0ull; acc[i][1] = 0ull; }

    constexpr int S = K / TK;
    if (tid < 64) {
        float4 ra = ldA(0);
        sA[0][a_k + 0][a_m] = ra.x; sA[0][a_k + 1][a_m] = ra.y;
        sA[0][a_k + 2][a_m] = ra.z; sA[0][a_k + 3][a_m] = ra.w;
    } else if (tid >= 128) {
        *(float4*)&sB[0][b_k][b_n] = ldB(0);
    }
    __syncthreads();
    for (int s = 0; s < S; ++s) {
        const int cur = s & 1;
        float4 nx;
        if (s + 1 < S) {
            if (tid < 64) nx = ldA((s + 1) * TK);
            else if (tid >= 128) nx = ldB((s + 1) * TK);
        }
#pragma unroll
        for (int k = 0; k < TK; ++k) {
            const float2 a = *(const float2*)&sA[cur][k][ty * 2];
            const ulonglong2 b = *(const ulonglong2*)&sB[cur][k][tx * 4];
            u64 ap;
            ap = pk2(a.x, a.x); fma2(acc[0][0], ap, b.x); fma2(acc[0][1], ap, b.y);
            ap = pk2(a.y, a.y); fma2(acc[1][0], ap, b.x); fma2(acc[1][1], ap, b.y);
        }
        if (s + 1 < S) {
            const int nxt = cur ^ 1;
            if (tid < 64) {
                sA[nxt][a_k + 0][a_m] = nx.x; sA[nxt][a_k + 1][a_m] = nx.y;
                sA[nxt][a_k + 2][a_m] = nx.z; sA[nxt][a_k + 3][a_m] = nx.w;
            } else if (tid >= 128) {
                *(float4*)&sB[nxt][b_k][b_n] = nx;
            }
        }
        __syncthreads();
    }
    const float4 bb = *(const float4*)(bias + n0 + tx * 4);
#pragma unroll
    for (int i = 0; i < 2; ++i) {
        float v0, v1, v2, v3;
        unpk2(v0, v1, acc[i][0]);
        unpk2(v2, v3, acc[i][1]);
        v0 += bb.x; v1 += bb.y; v2 += bb.z; v3 += bb.w;
        if (RELU) {
            v0 = fmaxf(v0, 0.f); v1 = fmaxf(v1, 0.f);
            v2 = fmaxf(v2, 0.f); v3 = fmaxf(v3, 0.f);
        }
        *(float4*)(C + (size_t)(m0 + ty * 2 + i) * NOUT + n0 + tx * 4) =
            make_float4(v0, v1, v2, v3);
    }
}

// ---------------- gemm_pq32: PQ[M,512] = A[M,256] @ {W_top|W_bot}, 32x64 tiles ----------------
__global__ __launch_bounds__(256)
void gemm_pq32(const float* __restrict__ A, const float* __restrict__ W,
               const float* __restrict__ bias, float* __restrict__ C)
{
    constexpr int K = 256, TK = 8;
    __shared__ __align__(16) float sA[2][TK][36];
    __shared__ __align__(16) float sB[2][TK][64];

    const int tid = threadIdx.x;
    const int m0 = blockIdx.x * 32;
    const int half = blockIdx.y >> 2;
    const int n0 = (blockIdx.y & 3) * 64;
    const float* Wb = W + (size_t)half * 256 * 256;

    const int a_m = (tid & 63) >> 1, a_k = (tid & 1) << 2;
    const int b_k = (tid & 127) >> 4, b_n = (tid & 15) << 2;
    const float* pr = A + (size_t)(m0 + a_m) * K;

    auto ldB = [&](int k0) -> float4 {
        return *(const float4*)(Wb + (size_t)(k0 + b_k) * 256 + n0 + b_n);
    };

    const int tx = tid & 15, ty = tid >> 4;
    u64 acc[2][2];
#pragma unroll
    for (int i = 0; i < 2; i++) { acc[i][0] = 0ull; acc[i][1] = 0ull; }

    if (tid < 64) {
        float4 ra = *(const float4*)(pr + a_k);
        sA[0][a_k + 0][a_m] = ra.x; sA[0][a_k + 1][a_m] = ra.y;
        sA[0][a_k + 2][a_m] = ra.z; sA[0][a_k + 3][a_m] = ra.w;
    } else if (tid >= 128) {
        *(float4*)&sB[0][b_k][b_n] = ldB(0);
    }
    __syncthreads();
    for (int s = 0; s < K / TK; ++s) {
        const int cur = s & 1;
        float4 nx;
        if (s + 1 < K / TK) {
            if (tid < 64) nx = *(const float4*)(pr + (s + 1) * TK + a_k);
            else if (tid >= 128) nx = ldB((s + 1) * TK);
        }
#pragma unroll
        for (int k = 0; k < TK; ++k) {
            const float2 a = *(const float2*)&sA[cur][k][ty * 2];
            const ulonglong2 b = *(const ulonglong2*)&sB[cur][k][tx * 4];
            u64 ap;
            ap = pk2(a.x, a.x); fma2(acc[0][0], ap, b.x); fma2(acc[0][1], ap, b.y);
            ap = pk2(a.y, a.y); fma2(acc[1][0], ap, b.x); fma2(acc[1][1], ap, b.y);
        }
        if (s + 1 < K / TK) {
            const int nxt = cur ^ 1;
            if (tid < 64) {
                sA[nxt][a_k + 0][a_m] = nx.x; sA[nxt][a_k + 1][a_m] = nx.y;
                sA[nxt][a_k + 2][a_m] = nx.z; sA[nxt][a_k + 3][a_m] = nx.w;
            } else if (tid >= 128) {
                *(float4*)&sB[nxt][b_k][b_n] = nx;
            }
        }
        __syncthreads();
    }
    float4 bb = half ? make_float4(0.f, 0.f, 0.f, 0.f)
                     : *(const float4*)(bias + n0 + tx * 4);
#pragma unroll
    for (int i = 0; i < 2; ++i) {
        float v0, v1, v2, v3;
        unpk2(v0, v1, acc[i][0]);
        unpk2(v2, v3, acc[i][1]);
        v0 += bb.x; v1 += bb.y; v2 += bb.z; v3 += bb.w;
        *(float4*)(C + (size_t)(m0 + ty * 2 + i) * 512 + half * 256 + n0 + tx * 4) =
            make_float4(v0, v1, v2, v3);
    }
}

// ---------------- launch ----------------
extern "C" void kernel_launch(void* const* d_in, const int* in_sizes, int n_in,
                              void* d_out, int out_size)
{
    (void)in_sizes; (void)n_in; (void)out_size;
    const float* x   = (const float*)d_in[0];
    const float* w1a = (const float*)d_in[3];
    const float* b1a = (const float*)d_in[4];
    const float* w1b = (const float*)d_in[5];
    const float* b1b = (const float*)d_in[6];
    const float* w2a = (const float*)d_in[7];
    const float* b2a = (const float*)d_in[8];
    const float* w2b = (const float*)d_in[9];
    const float* b2b = (const float*)d_in[10];
    const float* w3a = (const float*)d_in[11];
    const float* b3a = (const float*)d_in[12];
    const float* w3b = (const float*)d_in[13];
    const float* b3b = (const float*)d_in[14];
    const float* w4a = (const float*)d_in[15];
    const float* b4a = (const float*)d_in[16];
    const float* w4b = (const float*)d_in[17];
    const float* b4b = (const float*)d_in[18];
    const float* wo  = (const float*)d_in[19];
    const float* bo  = (const float*)d_in[20];
    float* out = (float*)d_out;

    float *xskipf, *nodeA, *nodeB, *pq; __half* wth;
    cudaGetSymbolAddress((void**)&xskipf, g_xskip);
    cudaGetSymbolAddress((void**)&nodeA, g_nodeA);
    cudaGetSymbolAddress((void**)&nodeB, g_nodeB);
    cudaGetSymbolAddress((void**)&pq,    g_pq);
    cudaGetSymbolAddress((void**)&wth,   g_wth);
    __half* xskip16 = (__half*)xskipf;

    __half* f2b = wth;               // w2b, K=256
    __half* f4c = wth + 256 * 256;   // w4a[512:768], K=256 (x_skip block)
    __half* f4b = wth + 512 * 256;   // w4b, K=256

    cudaFuncSetAttribute(fused2, cudaFuncAttributeMaxDynamicSharedMemorySize, F2_BYTES);
    cudaFuncSetAttribute(fused4, cudaFuncAttributeMaxDynamicSharedMemorySize, F4_BYTES);

    // convert+scatter weights into fp16 frag-ordered layout (single launch)
    wsplit3_k<<<768, 256>>>(w2b, w4a + 512 * 256, w4b, wth);

    const dim3 blk(256);
    const dim3 gN32(100, 4);
    const dim3 gPQ(100, 8);

    // Zero node accumulator (for fused2's in-kernel aggregation)
    zero_k<<<(B_ * N_ * H_) / 1024, 256>>>(nodeA, B_ * N_ * H_);

    // MLP1 on nodes (SIMT fp32, exact): x -> relu1 (in pq tmp) -> nodeB (=h)
    gemm_k32<MODE_X,  NIN_, H_, true ><<<gN32, blk>>>(x,  w1a, b1a, pq);     // pq as tmp
    gemm_k32<MODE_DIR, H_,  H_, false><<<gN32, blk>>>(pq, w1b, b1b, nodeB);

    // Node projections for MLP2: PQ = [h@w2a_top + b2a | h@w2a_bot]
    gemm_pq32<<<gPQ, blk>>>(nodeB, w2a, b2a, pq);

    // Fused MLP2 on edges + aggregation: x_skip (fp16) and nodeA += segsum/N
    fused2<<<2475, blk, F2_BYTES>>>(pq, f2b, b2b, xskip16, nodeA);

    // MLP3 on nodes (SIMT fp32): nodeA -> nodeB(relu) -> nodeA (=v)
    gemm_k32<MODE_DIR, H_, H_, true ><<<gN32, blk>>>(nodeA, w3a, b3a, nodeB);
    gemm_k32<MODE_DIR, H_, H_, false><<<gN32, blk>>>(nodeB, w3b, b3b, nodeA);

    // Node projections for MLP4: PQ = [v@w4a_top + b4a | v@w4a_mid]
    gemm_pq32<<<gPQ, blk>>>(nodeA, w4a, b4a, pq);

    // Fused MLP4 + output head
    fused4<<<2475, blk, F4_BYTES>>>(xskip16, pq, f4c, f4b, b4b, wo, bo, out);
}

// round 14
// speedup vs baseline: 1.0290x; 1.0290x over previous
#include <cuda_runtime.h>
#include <cuda_fp16.h>
#include <cstdint>

// Problem dims
#define B_   32
#define T_   50
#define N_   100
#define D_   4
#define E_   9900          // N*(N-1)
#define BE_  316800        // B*E
#define H_   256           // hidden
#define NIN_ 200           // T*D

// Scratch (device globals; no allocation allowed)
__device__ float  g_xskip[BE_ * H_ / 2];   // __half x_skip buffer (162 MB)
__device__ float  g_nodeA[B_ * N_ * H_];   // 3.3 MB
__device__ float  g_nodeB[B_ * N_ * H_];   // 3.3 MB
__device__ float  g_pq   [B_ * N_ * 512];  // P|Q node projections, 6.6 MB
__device__ __half g_wth  [768 * 256];      // frag-ordered fp16 weights: w2b|w4c|w4b

enum { MODE_DIR = 0, MODE_X = 1 };

typedef unsigned long long u64;

// ---------------- small PTX helpers ----------------
__device__ __forceinline__ uint32_t smem_to_u32(const void* p) {
    uint32_t a;
    asm("{ .reg .u64 t; cvta.to.shared.u64 t, %1; cvt.u32.u64 %0, t; }" : "=r"(a) : "l"(p));
    return a;
}
__device__ __forceinline__ uint32_t pkh2(float x, float y) {
    __half2 h = __floats2half2_rn(x, y);
    return *(uint32_t*)&h;
}
__device__ __forceinline__ void cp16(uint32_t s, const void* g) {
    asm volatile("cp.async.cg.shared.global [%0], [%1], 16;" :: "r"(s), "l"(g) : "memory");
}
__device__ __forceinline__ void cp_commit() { asm volatile("cp.async.commit_group;" ::: "memory"); }
__device__ __forceinline__ void cp_wait0()  { asm volatile("cp.async.wait_group 0;" ::: "memory"); }

__device__ __forceinline__ void mma_f16(float* c, const uint32_t* a, uint32_t b0, uint32_t b1) {
    asm volatile(
        "mma.sync.aligned.m16n8k16.row.col.f32.f16.f16.f32 "
        "{%0,%1,%2,%3}, {%4,%5,%6,%7}, {%8,%9}, {%0,%1,%2,%3};"
        : "+f"(c[0]), "+f"(c[1]), "+f"(c[2]), "+f"(c[3])
        : "r"(a[0]), "r"(a[1]), "r"(a[2]), "r"(a[3]), "r"(b0), "r"(b1));
}

// edge index helpers
__device__ __forceinline__ void edge_nodes(int m, int& bn_rcv, int& bn_snd) {
    int b = m / E_, e = m - b * E_;
    int rcv = e / (N_ - 1), jj = e - rcv * (N_ - 1);
    int snd = jj + (jj >= rcv ? 1 : 0);
    bn_rcv = b * N_ + rcv;
    bn_snd = b * N_ + snd;
}

// SIMT f32x2 primitives
__device__ __forceinline__ u64 pk2(float lo, float hi) {
    u64 r; asm("mov.b64 %0, {%1, %2};" : "=l"(r) : "f"(lo), "f"(hi)); return r;
}
__device__ __forceinline__ void fma2(u64& d, u64 a, u64 b) {
    asm("fma.rn.f32x2 %0, %1, %2, %0;" : "+l"(d) : "l"(a), "l"(b));
}
__device__ __forceinline__ void unpk2(float& lo, float& hi, u64 v) {
    asm("mov.b64 {%0, %1}, %2;" : "=f"(lo), "=f"(hi) : "l"(v));
}

// ---------------- zero kernel for node accumulator ----------------
__global__ void zero_k(float* __restrict__ p, int n)
{
    const int i = blockIdx.x * 1024 + threadIdx.x * 4;
    if (i < n) *(float4*)(p + i) = make_float4(0.f, 0.f, 0.f, 0.f);
}

// ==================== fused2: x_skip = relu(P[recv]+Q[send]) @ W2 + b2 ====================
// Also accumulates the edge->node mean into V (nodeA) via atomics.
// 256 threads = 8 warps (4m x 2n), warp tile 32x128.
// smem: hidden 128 x 132 b32 (67584 B) at 0; B[2] 16 KB each. total 100352 B.
#define F2_SMB(p) (67584u + (p) * 16384u)
#define F2_BYTES  100352

__global__ __launch_bounds__(256, 1)
void fused2(const float* __restrict__ PQ, const __half* __restrict__ W2,
            const float* __restrict__ b2v, __half* __restrict__ C,
            float* __restrict__ V)
{
    extern __shared__ char smem[];
    const uint32_t sbase = smem_to_u32(smem);
    const int tid = threadIdx.x;
    const int m0 = blockIdx.x * 128;

    auto stageB = [&](int t, int p) {
        const char* hs = (const char*)(W2 + (size_t)t * 8192);
        const uint32_t dh = sbase + F2_SMB(p);
#pragma unroll
        for (int i = 0; i < 4; ++i) {
            const int e4 = i * 256 + tid;
            cp16(dh + e4 * 16, hs + e4 * 16);
        }
    };

    stageB(0, 0);
    cp_commit();

    // ---- gather-add: hidden = relu(P[recv] + Q[send]) (bias pre-folded into P) ----
    {
        const int arow = tid >> 1, side = tid & 1;
        int bnr, bns; edge_nodes(m0 + arow, bnr, bns);
        const float4* Pr = (const float4*)(PQ + (size_t)bnr * 512 + side * 128);
        const float4* Qr = (const float4*)(PQ + (size_t)bns * 512 + 256 + side * 128);
        uint32_t* dst = (uint32_t*)smem + arow * 132 + side * 64;
#pragma unroll 8
        for (int j = 0; j < 32; ++j) {
            const float4 p = Pr[j], q = Qr[j];
            const float v0 = fmaxf(p.x + q.x, 0.f), v1 = fmaxf(p.y + q.y, 0.f);
            const float v2 = fmaxf(p.z + q.z, 0.f), v3 = fmaxf(p.w + q.w, 0.f);
            dst[2 * j]     = pkh2(v0, v1);
            dst[2 * j + 1] = pkh2(v2, v3);
        }
    }
    cp_wait0();
    __syncthreads();

    // ---- GEMM2: hidden[128,256] @ W2 ----
    const int wid = tid >> 5, lane = tid & 31;
    const int warp_m = wid >> 1, warp_n = wid & 1;
    const int g = lane >> 2, t4 = lane & 3;

    float acc[2][16][4];
#pragma unroll
    for (int i = 0; i < 2; i++)
#pragma unroll
        for (int j = 0; j < 16; j++)
#pragma unroll
            for (int c = 0; c < 4; c++) acc[i][j][c] = 0.f;

#pragma unroll 1
    for (int t2 = 0; t2 < 8; ++t2) {
        const int p = t2 & 1;
        if (t2 + 1 < 8) { stageB(t2 + 1, p ^ 1); cp_commit(); }
        {
            const uint32_t* sH = (const uint32_t*)smem;
            const uint2*    sB = (const uint2*)(smem + F2_SMB(p));
#pragma unroll
            for (int kk = 0; kk < 2; ++kk) {
                uint32_t a[2][4];
#pragma unroll
                for (int mt = 0; mt < 2; ++mt) {
                    const int r0 = warp_m * 32 + mt * 16 + g;
                    const int cb = t2 * 16 + kk * 8 + t4;
                    a[mt][0] = sH[r0 * 132 + cb];
                    a[mt][1] = sH[(r0 + 8) * 132 + cb];
                    a[mt][2] = sH[r0 * 132 + cb + 4];
                    a[mt][3] = sH[(r0 + 8) * 132 + cb + 4];
                }
#pragma unroll
                for (int nt = 0; nt < 16; ++nt) {
                    const int bi = warp_n * 1024 + ((nt * 2 + kk) * 32 + lane);
                    uint2 b = sB[bi];
#pragma unroll
                    for (int mt = 0; mt < 2; ++mt)
                        mma_f16(acc[mt][nt], a[mt], b.x, b.y);
                }
            }
        }
        cp_wait0();
        __syncthreads();
    }

    // epilogue: bias, fp16 store to gmem + smem (for aggregation)
    {
        uint32_t* sX = (uint32_t*)smem;    // hidden region dead; stride 132
#pragma unroll
        for (int mt = 0; mt < 2; ++mt) {
#pragma unroll
            for (int nt = 0; nt < 16; ++nt) {
                const int rl = warp_m * 32 + mt * 16 + g;
                const int col = warp_n * 128 + nt * 8 + t4 * 2;
                const float2 bb = *(const float2*)(b2v + col);
                const uint32_t h0 = pkh2(acc[mt][nt][0] + bb.x, acc[mt][nt][1] + bb.y);
                const uint32_t h1 = pkh2(acc[mt][nt][2] + bb.x, acc[mt][nt][3] + bb.y);
                *(uint32_t*)(C + (size_t)(m0 + rl) * 256 + col)     = h0;
                *(uint32_t*)(C + (size_t)(m0 + rl + 8) * 256 + col) = h1;
                sX[rl * 132 + (col >> 1)]       = h0;
                sX[(rl + 8) * 132 + (col >> 1)] = h1;
            }
        }
    }
    __syncthreads();

    // ---- aggregation: per node segment (bn = m/99, contiguous), sum/100, atomicAdd ----
    {
        const uint32_t* sX = (const uint32_t*)smem;
        const int cp  = tid & 127;      // column pair
        const int par = tid >> 7;       // segment parity
        const int bn0 = m0 / (N_ - 1);
        const int bn1 = (m0 + 127) / (N_ - 1);
        for (int bn = bn0 + par; bn <= bn1; bn += 2) {
            const int lo = max(bn * (N_ - 1) - m0, 0);
            const int hi = min(bn * (N_ - 1) + (N_ - 1) - m0, 128);
            float s0 = 0.f, s1 = 0.f;
            for (int r = lo; r < hi; ++r) {
                const uint32_t hv = sX[r * 132 + cp];
                __half2 h = *(const __half2*)&hv;
                float2 f = __half22float2(h);
                s0 += f.x; s1 += f.y;
            }
            atomicAdd(&V[(size_t)bn * 256 + cp * 2],     s0 * (1.0f / N_));
            atomicAdd(&V[(size_t)bn * 256 + cp * 2 + 1], s1 * (1.0f / N_));
        }
    }
}

// ==================== fused4 + output head ====================
// out[M,4] = (relu(xs@W1 + P4[recv]+Q4[send]) @ W2 + b2) @ wo + bo
#define F4_SMA(p) ((p) * 10240u)
#define F4_SMH    (20480u)
#define F4_SMB(p) (88064u + (p) * 16384u)
#define F4_BYTES  120832

__global__ __launch_bounds__(256, 1)
void fused4(const __half* __restrict__ XS, const float* __restrict__ PQ,
            const __half* __restrict__ W1, const __half* __restrict__ W2,
            const float* __restrict__ b2v, const float* __restrict__ wo,
            const float* __restrict__ bo, float* __restrict__ out)
{
    extern __shared__ char smem[];
    const uint32_t sbase = smem_to_u32(smem);
    const int tid = threadIdx.x;
    const int m0 = blockIdx.x * 128;

    const int arow = tid >> 1;
    const int kh   = (tid & 1) << 4;
    const __half* xrow = XS + (size_t)(m0 + arow) * 256;

    auto stageA = [&](int t, int p) {
        const uint32_t dst = sbase + F4_SMA(p) + (arow * 20 + (tid & 1) * 8) * 4;
        const char* src = (const char*)(xrow + t * 32 + kh);
        cp16(dst, src);
        cp16(dst + 16, src + 16);
    };
    auto stageB = [&](const __half* W, int t, int p) {
        const char* hs = (const char*)(W + (size_t)t * 8192);
        const uint32_t dh = sbase + F4_SMB(p);
#pragma unroll
        for (int i = 0; i < 4; ++i) {
            const int e4 = i * 256 + tid;
            cp16(dh + e4 * 16, hs + e4 * 16);
        }
    };

    const int wid = tid >> 5, lane = tid & 31;
    const int warp_m = wid >> 1, warp_n = wid & 1;
    const int g = lane >> 2, t4 = lane & 3;

    float acc[2][16][4];
#pragma unroll
    for (int i = 0; i < 2; i++)
#pragma unroll
        for (int j = 0; j < 16; j++)
#pragma unroll
            for (int c = 0; c < 4; c++) acc[i][j][c] = 0.f;

    // ---- GEMM1: xs[128,256] @ W1 ----
    stageA(0, 0); stageB(W1, 0, 0);
    cp_commit();
    cp_wait0();
    __syncthreads();

#pragma unroll 1
    for (int t = 0; t < 8; ++t) {
        const int p = t & 1;
        if (t + 1 < 8) { stageA(t + 1, p ^ 1); stageB(W1, t + 1, p ^ 1); cp_commit(); }
        {
            const uint32_t* sA = (const uint32_t*)(smem + F4_SMA(p));
            const uint2*    sB = (const uint2*)(smem + F4_SMB(p));
#pragma unroll
            for (int kk = 0; kk < 2; ++kk) {
                uint32_t a[2][4];
#pragma unroll
                for (int mt = 0; mt < 2; ++mt) {
                    const int base = ((warp_m * 2 + mt) * 16 + g) * 20 + kk * 8 + t4;
                    a[mt][0] = sA[base];
                    a[mt][1] = sA[base + 8 * 20];
                    a[mt][2] = sA[base + 4];
                    a[mt][3] = sA[base + 8 * 20 + 4];
                }
#pragma unroll
                for (int nt = 0; nt < 16; ++nt) {
                    const int bi = warp_n * 1024 + ((nt * 2 + kk) * 32 + lane);
                    uint2 b = sB[bi];
#pragma unroll
                    for (int mt = 0; mt < 2; ++mt)
                        mma_f16(acc[mt][nt], a[mt], b.x, b.y);
                }
            }
        }
        cp_wait0();
        __syncthreads();
    }

    // prefetch GEMM2 B tile 0 while doing epilogue 1
    stageB(W2, 0, 0);
    cp_commit();

    // ---- epilogue 1: hidden = relu(acc + P4[recv] + Q4[send]) (b4a folded into P4) ----
    {
        uint32_t* sH = (uint32_t*)(smem + F4_SMH);
#pragma unroll
        for (int mt = 0; mt < 2; ++mt) {
#pragma unroll
            for (int rr = 0; rr < 2; ++rr) {
                const int rloc = warp_m * 32 + mt * 16 + g + rr * 8;
                int bnr, bns; edge_nodes(m0 + rloc, bnr, bns);
                const float* Pr = PQ + (size_t)bnr * 512;
                const float* Qr = PQ + (size_t)bns * 512 + 256;
#pragma unroll
                for (int nt = 0; nt < 16; ++nt) {
                    const int col = warp_n * 128 + nt * 8 + t4 * 2;
                    const float2 p = *(const float2*)(Pr + col);
                    const float2 q = *(const float2*)(Qr + col);
                    const float v0 = fmaxf(acc[mt][nt][rr * 2 + 0] + p.x + q.x, 0.f);
                    const float v1 = fmaxf(acc[mt][nt][rr * 2 + 1] + p.y + q.y, 0.f);
                    sH[rloc * 132 + warp_n * 64 + nt * 4 + t4] = pkh2(v0, v1);
                }
            }
        }
    }
#pragma unroll
    for (int i = 0; i < 2; i++)
#pragma unroll
        for (int j = 0; j < 16; j++)
#pragma unroll
            for (int c = 0; c < 4; c++) acc[i][j][c] = 0.f;

    cp_wait0();
    __syncthreads();

    // ---- GEMM2: hidden @ W2 ----
#pragma unroll 1
    for (int t2 = 0; t2 < 8; ++t2) {
        const int p = t2 & 1;
        if (t2 + 1 < 8) { stageB(W2, t2 + 1, p ^ 1); cp_commit(); }
        {
            const uint32_t* sH = (const uint32_t*)(smem + F4_SMH);
            const uint2*    sB = (const uint2*)(smem + F4_SMB(p));
#pragma unroll
            for (int kk = 0; kk < 2; ++kk) {
                uint32_t a[2][4];
#pragma unroll
                for (int mt = 0; mt < 2; ++mt) {
                    const int r0 = warp_m * 32 + mt * 16 + g;
                    const int cb = t2 * 16 + kk * 8 + t4;
                    a[mt][0] = sH[r0 * 132 + cb];
                    a[mt][1] = sH[(r0 + 8) * 132 + cb];
                    a[mt][2] = sH[r0 * 132 + cb + 4];
                    a[mt][3] = sH[(r0 + 8) * 132 + cb + 4];
                }
#pragma unroll
                for (int nt = 0; nt < 16; ++nt) {
                    const int bi = warp_n * 1024 + ((nt * 2 + kk) * 32 + lane);
                    uint2 b = sB[bi];
#pragma unroll
                    for (int mt = 0; mt < 2; ++mt)
                        mma_f16(acc[mt][nt], a[mt], b.x, b.y);
                }
            }
        }
        cp_wait0();
        __syncthreads();
    }

    // ---- epilogue 2: output head. out = (acc + b4b) @ wo + bo ----
    {
        float p[2][2][4];
#pragma unroll
        for (int mt = 0; mt < 2; ++mt)
#pragma unroll
            for (int rr = 0; rr < 2; ++rr)
#pragma unroll
                for (int j = 0; j < 4; ++j) p[mt][rr][j] = 0.f;

#pragma unroll
        for (int nt = 0; nt < 16; ++nt) {
            const int col = warp_n * 128 + nt * 8 + t4 * 2;
            const float2 bb = *(const float2*)(b2v + col);
            const float4 w0 = *(const float4*)(wo + col * 4);
            const float4 w1 = *(const float4*)(wo + (col + 1) * 4);
#pragma unroll
            for (int mt = 0; mt < 2; ++mt)
#pragma unroll
                for (int rr = 0; rr < 2; ++rr) {
                    const float v0 = acc[mt][nt][rr * 2 + 0] + bb.x;
                    const float v1 = acc[mt][nt][rr * 2 + 1] + bb.y;
                    p[mt][rr][0] += v0 * w0.x + v1 * w1.x;
                    p[mt][rr][1] += v0 * w0.y + v1 * w1.y;
                    p[mt][rr][2] += v0 * w0.z + v1 * w1.z;
                    p[mt][rr][3] += v0 * w0.w + v1 * w1.w;
                }
        }
        // reduce over t4 lanes (lane = g*4 + t4)
#pragma unroll
        for (int mt = 0; mt < 2; ++mt)
#pragma unroll
            for (int rr = 0; rr < 2; ++rr)
#pragma unroll
                for (int j = 0; j < 4; ++j) {
                    float v = p[mt][rr][j];
                    v += __shfl_xor_sync(0xffffffffu, v, 1);
                    v += __shfl_xor_sync(0xffffffffu, v, 2);
                    p[mt][rr][j] = v;
                }
        float* sO = (float*)smem;     // reuse dead A region, 4 KB
        if (t4 == 0) {
#pragma unroll
            for (int mt = 0; mt < 2; ++mt)
#pragma unroll
                for (int rr = 0; rr < 2; ++rr) {
                    const int rloc = warp_m * 32 + mt * 16 + rr * 8 + g;
#pragma unroll
                    for (int j = 0; j < 4; ++j)
                        sO[rloc * 8 + warp_n * 4 + j] = p[mt][rr][j];
                }
        }
        __syncthreads();
#pragma unroll
        for (int it = 0; it < 2; ++it) {
            const int idx = tid + it * 256;
            const int row = idx >> 2, j = idx & 3;
            out[(size_t)(m0 + row) * 4 + j] = sO[row * 8 + j] + sO[row * 8 + 4 + j] + bo[j];
        }
    }
}

// ---------------- merged weight fp16-convert + frag-order scatter (3x K=256) ----------------
__global__ void wsplit3_k(const float* __restrict__ w0, const float* __restrict__ w1s,
                          const float* __restrict__ w2s, __half* __restrict__ oh)
{
    const int grp = blockIdx.x >> 8;                 // 0,1,2
    const int lb  = blockIdx.x & 255;
    const float* w = (grp == 0) ? w0 : (grp == 1) ? w1s : w2s;
    __half* dstb = oh + (size_t)grp * 256 * 256;
    const int idx = lb * 256 + threadIdx.x;          // = k*256 + n
    const int k = idx >> 8, n = idx & 255;
    const __half hv = __float2half_rn(w[idx]);
    const int ny = n >> 7, nr = n & 127;
    const int nt = nr >> 3, gg = nr & 7;
    const int s = k >> 5, kr = k & 31;
    const int kk = kr >> 4, kr16 = kr & 15;
    const int reg = (kr16 >= 8) ? 1 : 0;
    const int t4 = (kr16 & 7) >> 1;
    const int hp = kr16 & 1;
    const int lane = gg * 4 + t4;
    const int dst = (s * 2 + ny) * 4096 + ((nt * 2 + kk) * 32 + lane) * 4 + reg * 2 + hp;
    dstb[dst] = hv;
}

// ---------------- SIMT f32x2 GEMM, 64x64 tiles (node layers, exact fp32) ----------------
template<int MODE, int K, int NOUT, bool RELU>
__global__ __launch_bounds__(256)
void gemm_k64(const float* __restrict__ A, const float* __restrict__ W,
              const float* __restrict__ bias, float* __restrict__ C)
{
    constexpr int TK = 8;
    __shared__ __align__(16) float sA[2][TK][68];
    __shared__ __align__(16) float sB[2][TK][64];

    const int tid = threadIdx.x;
    const int m0 = blockIdx.x * 64, n0 = blockIdx.y * 64;

    const int a_m = (tid & 127) >> 1, a_k = (tid & 1) << 2;
    const int b_k = (tid & 127) >> 4, b_n = (tid & 15) << 2;

    const int m = m0 + a_m;
    const float* pr;
    if (MODE == MODE_DIR) {
        pr = A + (size_t)m * K;
    } else { // MODE_X
        int b = m / N_, n = m - b * N_;
        pr = A + (size_t)b * (T_ * N_ * D_) + (size_t)n * D_;
    }
    auto ldA = [&](int k0) -> float4 {
        const int k = k0 + a_k;
        if (MODE == MODE_DIR) return *(const float4*)(pr + k);
        return *(const float4*)(pr + (size_t)(k >> 2) * (N_ * D_));
    };
    auto ldB = [&](int k0) -> float4 {
        return *(const float4*)(W + (size_t)(k0 + b_k) * NOUT + n0 + b_n);
    };

    const int tx = tid & 15, ty = tid >> 4;
    u64 acc[4][2];
#pragma unroll
    for (int i = 0; i < 4; i++) { acc[i][0] = 0ull; acc[i][1] = 0ull; }

    constexpr int S = K / TK;
    if (tid < 128) {
        float4 ra = ldA(0);
        sA[0][a_k + 0][a_m] = ra.x; sA[0][a_k + 1][a_m] = ra.y;
        sA[0][a_k + 2][a_m] = ra.z; sA[0][a_k + 3][a_m] = ra.w;
    } else {
        *(float4*)&sB[0][b_k][b_n] = ldB(0);
    }
    __syncthreads();
    for (int s = 0; s < S; ++s) {
        const int cur = s & 1;
        float4 nx;
        if (s + 1 < S) nx = (tid < 128) ? ldA((s + 1) * TK) : ldB((s + 1) * TK);
#pragma unroll
        for (int k = 0; k < TK; ++k) {
            const float4 a = *(const float4*)&sA[cur][k][ty * 4];
            const ulonglong2 b = *(const ulonglong2*)&sB[cur][k][tx * 4];
            u64 ap;
            ap = pk2(a.x, a.x); fma2(acc[0][0], ap, b.x); fma2(acc[0][1], ap, b.y);
            ap = pk2(a.y, a.y); fma2(acc[1][0], ap, b.x); fma2(acc[1][1], ap, b.y);
            ap = pk2(a.z, a.z); fma2(acc[2][0], ap, b.x); fma2(acc[2][1], ap, b.y);
            ap = pk2(a.w, a.w); fma2(acc[3][0], ap, b.x); fma2(acc[3][1], ap, b.y);
        }
        if (s + 1 < S) {
            const int nxt = cur ^ 1;
            if (tid < 128) {
                sA[nxt][a_k + 0][a_m] = nx.x; sA[nxt][a_k + 1][a_m] = nx.y;
                sA[nxt][a_k + 2][a_m] = nx.z; sA[nxt][a_k + 3][a_m] = nx.w;
            } else {
                *(float4*)&sB[nxt][b_k][b_n] = nx;
            }
        }
        __syncthreads();
    }
    const float4 bb = *(const float4*)(bias + n0 + tx * 4);
#pragma unroll
    for (int i = 0; i < 4; ++i) {
        float v0, v1, v2, v3;
        unpk2(v0, v1, acc[i][0]);
        unpk2(v2, v3, acc[i][1]);
        v0 += bb.x; v1 += bb.y; v2 += bb.z; v3 += bb.w;
        if (RELU) {
            v0 = fmaxf(v0, 0.f); v1 = fmaxf(v1, 0.f);
            v2 = fmaxf(v2, 0.f); v3 = fmaxf(v3, 0.f);
        }
        *(float4*)(C + (size_t)(m0 + ty * 4 + i) * NOUT + n0 + tx * 4) =
            make_float4(v0, v1, v2, v3);
    }
}

// ---------------- gemm_pq64: PQ[M,512] = A[M,256] @ {W_top|W_bot} ----------------
__global__ __launch_bounds__(256)
void gemm_pq64(const float* __restrict__ A, const float* __restrict__ W,
               const float* __restrict__ bias, float* __restrict__ C)
{
    constexpr int K = 256, TK = 8;
    __shared__ __align__(16) float sA[2][TK][68];
    __shared__ __align__(16) float sB[2][TK][64];

    const int tid = threadIdx.x;
    const int m0 = blockIdx.x * 64;
    const int half = blockIdx.y >> 2;
    const int n0 = (blockIdx.y & 3) * 64;
    const float* Wb = W + (size_t)half * 256 * 256;

    const int a_m = (tid & 127) >> 1, a_k = (tid & 1) << 2;
    const int b_k = (tid & 127) >> 4, b_n = (tid & 15) << 2;
    const float* pr = A + (size_t)(m0 + a_m) * K;

    auto ldB = [&](int k0) -> float4 {
        return *(const float4*)(Wb + (size_t)(k0 + b_k) * 256 + n0 + b_n);
    };

    const int tx = tid & 15, ty = tid >> 4;
    u64 acc[4][2];
#pragma unroll
    for (int i = 0; i < 4; i++) { acc[i][0] = 0ull; acc[i][1] = 0ull; }

    if (tid < 128) {
        float4 ra = *(const float4*)(pr + a_k);
        sA[0][a_k + 0][a_m] = ra.x; sA[0][a_k + 1][a_m] = ra.y;
        sA[0][a_k + 2][a_m] = ra.z; sA[0][a_k + 3][a_m] = ra.w;
    } else {
        *(float4*)&sB[0][b_k][b_n] = ldB(0);
    }
    __syncthreads();
    for (int s = 0; s < K / TK; ++s) {
        const int cur = s & 1;
        float4 nx;
        if (s + 1 < K / TK)
            nx = (tid < 128) ? *(const float4*)(pr + (s + 1) * TK + a_k) : ldB((s + 1) * TK);
#pragma unroll
        for (int k = 0; k < TK; ++k) {
            const float4 a = *(const float4*)&sA[cur][k][ty * 4];
            const ulonglong2 b = *(const ulonglong2*)&sB[cur][k][tx * 4];
            u64 ap;
            ap = pk2(a.x, a.x); fma2(acc[0][0], ap, b.x); fma2(acc[0][1], ap, b.y);
            ap = pk2(a.y, a.y); fma2(acc[1][0], ap, b.x); fma2(acc[1][1], ap, b.y);
            ap = pk2(a.z, a.z); fma2(acc[2][0], ap, b.x); fma2(acc[2][1], ap, b.y);
            ap = pk2(a.w, a.w); fma2(acc[3][0], ap, b.x); fma2(acc[3][1], ap, b.y);
        }
        if (s + 1 < K / TK) {
            const int nxt = cur ^ 1;
            if (tid < 128) {
                sA[nxt][a_k + 0][a_m] = nx.x; sA[nxt][a_k + 1][a_m] = nx.y;
                sA[nxt][a_k + 2][a_m] = nx.z; sA[nxt][a_k + 3][a_m] = nx.w;
            } else {
                *(float4*)&sB[nxt][b_k][b_n] = nx;
            }
        }
        __syncthreads();
    }
    float4 bb = half ? make_float4(0.f, 0.f, 0.f, 0.f)
                     : *(const float4*)(bias + n0 + tx * 4);
#pragma unroll
    for (int i = 0; i < 4; ++i) {
        float v0, v1, v2, v3;
        unpk2(v0, v1, acc[i][0]);
        unpk2(v2, v3, acc[i][1]);
        v0 += bb.x; v1 += bb.y; v2 += bb.z; v3 += bb.w;
        *(float4*)(C + (size_t)(m0 + ty * 4 + i) * 512 + half * 256 + n0 + tx * 4) =
            make_float4(v0, v1, v2, v3);
    }
}

// ---------------- launch ----------------
extern "C" void kernel_launch(void* const* d_in, const int* in_sizes, int n_in,
                              void* d_out, int out_size)
{
    (void)in_sizes; (void)n_in; (void)out_size;
    const float* x   = (const float*)d_in[0];
    const float* w1a = (const float*)d_in[3];
    const float* b1a = (const float*)d_in[4];
    const float* w1b = (const float*)d_in[5];
    const float* b1b = (const float*)d_in[6];
    const float* w2a = (const float*)d_in[7];
    const float* b2a = (const float*)d_in[8];
    const float* w2b = (const float*)d_in[9];
    const float* b2b = (const float*)d_in[10];
    const float* w3a = (const float*)d_in[11];
    const float* b3a = (const float*)d_in[12];
    const float* w3b = (const float*)d_in[13];
    const float* b3b = (const float*)d_in[14];
    const float* w4a = (const float*)d_in[15];
    const float* b4a = (const float*)d_in[16];
    const float* w4b = (const float*)d_in[17];
    const float* b4b = (const float*)d_in[18];
    const float* wo  = (const float*)d_in[19];
    const float* bo  = (const float*)d_in[20];
    float* out = (float*)d_out;

    float *xskipf, *nodeA, *nodeB, *pq; __half* wth;
    cudaGetSymbolAddress((void**)&xskipf, g_xskip);
    cudaGetSymbolAddress((void**)&nodeA, g_nodeA);
    cudaGetSymbolAddress((void**)&nodeB, g_nodeB);
    cudaGetSymbolAddress((void**)&pq,    g_pq);
    cudaGetSymbolAddress((void**)&wth,   g_wth);
    __half* xskip16 = (__half*)xskipf;

    __half* f2b = wth;               // w2b, K=256
    __half* f4c = wth + 256 * 256;   // w4a[512:768], K=256 (x_skip block)
    __half* f4b = wth + 512 * 256;   // w4b, K=256

    cudaFuncSetAttribute(fused2, cudaFuncAttributeMaxDynamicSharedMemorySize, F2_BYTES);
    cudaFuncSetAttribute(fused4, cudaFuncAttributeMaxDynamicSharedMemorySize, F4_BYTES);

    const dim3 blk(256);
    const dim3 gN64(50, 4);
    const dim3 gPQ(50, 8);

    // Zero node accumulator first (overlaps with weight prep wave)
    zero_k<<<(B_ * N_ * H_) / 1024, 256>>>(nodeA, B_ * N_ * H_);

    // convert+scatter weights into fp16 frag-ordered layout (single launch)
    wsplit3_k<<<768, 256>>>(w2b, w4a + 512 * 256, w4b, wth);

    // MLP1 on nodes (SIMT fp32, exact): x -> relu1 (in pq tmp) -> nodeB (=h)
    gemm_k64<MODE_X,  NIN_, H_, true ><<<gN64, blk>>>(x,  w1a, b1a, pq);     // pq as tmp
    gemm_k64<MODE_DIR, H_,  H_, false><<<gN64, blk>>>(pq, w1b, b1b, nodeB);

    // Node projections for MLP2: PQ = [h@w2a_top + b2a | h@w2a_bot]
    gemm_pq64<<<gPQ, blk>>>(nodeB, w2a, b2a, pq);

    // Fused MLP2 on edges + aggregation: x_skip (fp16) and nodeA += segsum/N
    fused2<<<2475, blk, F2_BYTES>>>(pq, f2b, b2b, xskip16, nodeA);

    // MLP3 on nodes (SIMT fp32): nodeA -> nodeB(relu) -> nodeA (=v)
    gemm_k64<MODE_DIR, H_, H_, true ><<<gN64, blk>>>(nodeA, w3a, b3a, nodeB);
    gemm_k64<MODE_DIR, H_, H_, false><<<gN64, blk>>>(nodeB, w3b, b3b, nodeA);

    // Node projections for MLP4: PQ = [v@w4a_top + b4a | v@w4a_mid]
    gemm_pq64<<<gPQ, blk>>>(nodeA, w4a, b4a, pq);

    // Fused MLP4 + output head
    fused4<<<2475, blk, F4_BYTES>>>(xskip16, pq, f4c, f4b, b4b, wo, bo, out);
}

// round 15
// speedup vs baseline: 1.0716x; 1.0413x over previous
#include <cuda_runtime.h>
#include <cuda_fp16.h>
#include <cstdint>

// Problem dims
#define B_   32
#define T_   50
#define N_   100
#define D_   4
#define E_   9900          // N*(N-1)
#define BE_  316800        // B*E
#define H_   256           // hidden
#define NIN_ 200           // T*D

// Scratch (device globals; no allocation allowed)
__device__ float  g_xskip[BE_ * H_ / 2];   // __half x_skip buffer (162 MB)
__device__ float  g_nodeA[B_ * N_ * H_];   // 3.3 MB
__device__ float  g_nodeB[B_ * N_ * H_];   // 3.3 MB
__device__ float  g_pq   [B_ * N_ * 512];  // P|Q node projections, 6.6 MB
__device__ __half g_wth  [768 * 256];      // frag-ordered fp16 weights: w2b|w4c|w4b

enum { MODE_DIR = 0, MODE_X = 1 };

typedef unsigned long long u64;

// ---------------- small PTX helpers ----------------
__device__ __forceinline__ uint32_t smem_to_u32(const void* p) {
    uint32_t a;
    asm("{ .reg .u64 t; cvta.to.shared.u64 t, %1; cvt.u32.u64 %0, t; }" : "=r"(a) : "l"(p));
    return a;
}
__device__ __forceinline__ uint32_t pkh2(float x, float y) {
    __half2 h = __floats2half2_rn(x, y);
    return *(uint32_t*)&h;
}
__device__ __forceinline__ void cp16(uint32_t s, const void* g) {
    asm volatile("cp.async.cg.shared.global [%0], [%1], 16;" :: "r"(s), "l"(g) : "memory");
}
__device__ __forceinline__ void cp_commit() { asm volatile("cp.async.commit_group;" ::: "memory"); }
__device__ __forceinline__ void cp_wait0()  { asm volatile("cp.async.wait_group 0;" ::: "memory"); }

__device__ __forceinline__ void mma_f16(float* c, const uint32_t* a, uint32_t b0, uint32_t b1) {
    asm volatile(
        "mma.sync.aligned.m16n8k16.row.col.f32.f16.f16.f32 "
        "{%0,%1,%2,%3}, {%4,%5,%6,%7}, {%8,%9}, {%0,%1,%2,%3};"
        : "+f"(c[0]), "+f"(c[1]), "+f"(c[2]), "+f"(c[3])
        : "r"(a[0]), "r"(a[1]), "r"(a[2]), "r"(a[3]), "r"(b0), "r"(b1));
}

// edge index helpers
__device__ __forceinline__ void edge_nodes(int m, int& bn_rcv, int& bn_snd) {
    int b = m / E_, e = m - b * E_;
    int rcv = e / (N_ - 1), jj = e - rcv * (N_ - 1);
    int snd = jj + (jj >= rcv ? 1 : 0);
    bn_rcv = b * N_ + rcv;
    bn_snd = b * N_ + snd;
}

// SIMT f32x2 primitives
__device__ __forceinline__ u64 pk2(float lo, float hi) {
    u64 r; asm("mov.b64 %0, {%1, %2};" : "=l"(r) : "f"(lo), "f"(hi)); return r;
}
__device__ __forceinline__ void fma2(u64& d, u64 a, u64 b) {
    asm("fma.rn.f32x2 %0, %1, %2, %0;" : "+l"(d) : "l"(a), "l"(b));
}
__device__ __forceinline__ void unpk2(float& lo, float& hi, u64 v) {
    asm("mov.b64 {%0, %1}, %2;" : "=f"(lo), "=f"(hi) : "l"(v));
}

// ---------------- zero kernel for node accumulator ----------------
__global__ void zero_k(float* __restrict__ p, int n)
{
    const int i = blockIdx.x * 1024 + threadIdx.x * 4;
    if (i < n) *(float4*)(p + i) = make_float4(0.f, 0.f, 0.f, 0.f);
}

// ==================== fused2: x_skip = relu(P[recv]+Q[send]) @ W2 + b2 ====================
// Also accumulates the edge->node mean into V (nodeA) via atomics.
// 256 threads = 8 warps (4m x 2n), warp tile 32x128.
// smem: hidden 128 x 132 b32 (67584 B) at 0; B[2] 16 KB each. total 100352 B.
#define F2_SMB(p) (67584u + (p) * 16384u)
#define F2_BYTES  100352

__global__ __launch_bounds__(256, 1)
void fused2(const float* __restrict__ PQ, const __half* __restrict__ W2,
            const float* __restrict__ b2v, __half* __restrict__ C,
            float* __restrict__ V)
{
    extern __shared__ char smem[];
    const uint32_t sbase = smem_to_u32(smem);
    const int tid = threadIdx.x;
    const int m0 = blockIdx.x * 128;

    auto stageB = [&](int t, int p) {
        const char* hs = (const char*)(W2 + (size_t)t * 8192);
        const uint32_t dh = sbase + F2_SMB(p);
#pragma unroll
        for (int i = 0; i < 4; ++i) {
            const int e4 = i * 256 + tid;
            cp16(dh + e4 * 16, hs + e4 * 16);
        }
    };

    stageB(0, 0);
    cp_commit();

    // ---- gather-add: hidden = relu(P[recv] + Q[send]) (bias pre-folded into P) ----
    {
        const int arow = tid >> 1, side = tid & 1;
        int bnr, bns; edge_nodes(m0 + arow, bnr, bns);
        const float4* Pr = (const float4*)(PQ + (size_t)bnr * 512 + side * 128);
        const float4* Qr = (const float4*)(PQ + (size_t)bns * 512 + 256 + side * 128);
        uint32_t* dst = (uint32_t*)smem + arow * 132 + side * 64;
#pragma unroll 8
        for (int j = 0; j < 32; ++j) {
            const float4 p = Pr[j], q = Qr[j];
            const float v0 = fmaxf(p.x + q.x, 0.f), v1 = fmaxf(p.y + q.y, 0.f);
            const float v2 = fmaxf(p.z + q.z, 0.f), v3 = fmaxf(p.w + q.w, 0.f);
            dst[2 * j]     = pkh2(v0, v1);
            dst[2 * j + 1] = pkh2(v2, v3);
        }
    }
    cp_wait0();
    __syncthreads();

    // ---- GEMM2: hidden[128,256] @ W2 ----
    const int wid = tid >> 5, lane = tid & 31;
    const int warp_m = wid >> 1, warp_n = wid & 1;
    const int g = lane >> 2, t4 = lane & 3;

    float acc[2][16][4];
#pragma unroll
    for (int i = 0; i < 2; i++)
#pragma unroll
        for (int j = 0; j < 16; j++)
#pragma unroll
            for (int c = 0; c < 4; c++) acc[i][j][c] = 0.f;

#pragma unroll 1
    for (int t2 = 0; t2 < 8; ++t2) {
        const int p = t2 & 1;
        if (t2 + 1 < 8) { stageB(t2 + 1, p ^ 1); cp_commit(); }
        {
            const uint32_t* sH = (const uint32_t*)smem;
            const uint2*    sB = (const uint2*)(smem + F2_SMB(p));
#pragma unroll
            for (int kk = 0; kk < 2; ++kk) {
                uint32_t a[2][4];
#pragma unroll
                for (int mt = 0; mt < 2; ++mt) {
                    const int r0 = warp_m * 32 + mt * 16 + g;
                    const int cb = t2 * 16 + kk * 8 + t4;
                    a[mt][0] = sH[r0 * 132 + cb];
                    a[mt][1] = sH[(r0 + 8) * 132 + cb];
                    a[mt][2] = sH[r0 * 132 + cb + 4];
                    a[mt][3] = sH[(r0 + 8) * 132 + cb + 4];
                }
#pragma unroll
                for (int nt = 0; nt < 16; ++nt) {
                    const int bi = warp_n * 1024 + ((nt * 2 + kk) * 32 + lane);
                    uint2 b = sB[bi];
#pragma unroll
                    for (int mt = 0; mt < 2; ++mt)
                        mma_f16(acc[mt][nt], a[mt], b.x, b.y);
                }
            }
        }
        cp_wait0();
        __syncthreads();
    }

    // epilogue: bias, fp16 store to gmem + smem (for aggregation)
    {
        uint32_t* sX = (uint32_t*)smem;    // hidden region dead; stride 132
#pragma unroll
        for (int mt = 0; mt < 2; ++mt) {
#pragma unroll
            for (int nt = 0; nt < 16; ++nt) {
                const int rl = warp_m * 32 + mt * 16 + g;
                const int col = warp_n * 128 + nt * 8 + t4 * 2;
                const float2 bb = *(const float2*)(b2v + col);
                const uint32_t h0 = pkh2(acc[mt][nt][0] + bb.x, acc[mt][nt][1] + bb.y);
                const uint32_t h1 = pkh2(acc[mt][nt][2] + bb.x, acc[mt][nt][3] + bb.y);
                *(uint32_t*)(C + (size_t)(m0 + rl) * 256 + col)     = h0;
                *(uint32_t*)(C + (size_t)(m0 + rl + 8) * 256 + col) = h1;
                sX[rl * 132 + (col >> 1)]       = h0;
                sX[(rl + 8) * 132 + (col >> 1)] = h1;
            }
        }
    }
    __syncthreads();

    // ---- aggregation: per node segment (bn = m/99, contiguous), sum/100, atomicAdd ----
    {
        const uint32_t* sX = (const uint32_t*)smem;
        const int cp  = tid & 127;      // column pair
        const int par = tid >> 7;       // segment parity
        const int bn0 = m0 / (N_ - 1);
        const int bn1 = (m0 + 127) / (N_ - 1);
        for (int bn = bn0 + par; bn <= bn1; bn += 2) {
            const int lo = max(bn * (N_ - 1) - m0, 0);
            const int hi = min(bn * (N_ - 1) + (N_ - 1) - m0, 128);
            float s0 = 0.f, s1 = 0.f;
            for (int r = lo; r < hi; ++r) {
                const uint32_t hv = sX[r * 132 + cp];
                __half2 h = *(const __half2*)&hv;
                float2 f = __half22float2(h);
                s0 += f.x; s1 += f.y;
            }
            atomicAdd(&V[(size_t)bn * 256 + cp * 2],     s0 * (1.0f / N_));
            atomicAdd(&V[(size_t)bn * 256 + cp * 2 + 1], s1 * (1.0f / N_));
        }
    }
}

// ==================== fused4 + output head ====================
// out[M,4] = (relu(xs@W1 + P4[recv]+Q4[send]) @ W2 + b2) @ wo + bo
#define F4_SMA(p) ((p) * 10240u)
#define F4_SMH    (20480u)
#define F4_SMB(p) (88064u + (p) * 16384u)
#define F4_BYTES  120832

__global__ __launch_bounds__(256, 1)
void fused4(const __half* __restrict__ XS, const float* __restrict__ PQ,
            const __half* __restrict__ W1, const __half* __restrict__ W2,
            const float* __restrict__ b2v, const float* __restrict__ wo,
            const float* __restrict__ bo, float* __restrict__ out)
{
    extern __shared__ char smem[];
    const uint32_t sbase = smem_to_u32(smem);
    const int tid = threadIdx.x;
    const int m0 = blockIdx.x * 128;

    const int arow = tid >> 1;
    const int kh   = (tid & 1) << 4;
    const __half* xrow = XS + (size_t)(m0 + arow) * 256;

    auto stageA = [&](int t, int p) {
        const uint32_t dst = sbase + F4_SMA(p) + (arow * 20 + (tid & 1) * 8) * 4;
        const char* src = (const char*)(xrow + t * 32 + kh);
        cp16(dst, src);
        cp16(dst + 16, src + 16);
    };
    auto stageB = [&](const __half* W, int t, int p) {
        const char* hs = (const char*)(W + (size_t)t * 8192);
        const uint32_t dh = sbase + F4_SMB(p);
#pragma unroll
        for (int i = 0; i < 4; ++i) {
            const int e4 = i * 256 + tid;
            cp16(dh + e4 * 16, hs + e4 * 16);
        }
    };

    const int wid = tid >> 5, lane = tid & 31;
    const int warp_m = wid >> 1, warp_n = wid & 1;
    const int g = lane >> 2, t4 = lane & 3;

    float acc[2][16][4];
#pragma unroll
    for (int i = 0; i < 2; i++)
#pragma unroll
        for (int j = 0; j < 16; j++)
#pragma unroll
            for (int c = 0; c < 4; c++) acc[i][j][c] = 0.f;

    // ---- GEMM1: xs[128,256] @ W1 ----
    stageA(0, 0); stageB(W1, 0, 0);
    cp_commit();
    cp_wait0();
    __syncthreads();

#pragma unroll 1
    for (int t = 0; t < 8; ++t) {
        const int p = t & 1;
        if (t + 1 < 8) { stageA(t + 1, p ^ 1); stageB(W1, t + 1, p ^ 1); cp_commit(); }
        {
            const uint32_t* sA = (const uint32_t*)(smem + F4_SMA(p));
            const uint2*    sB = (const uint2*)(smem + F4_SMB(p));
#pragma unroll
            for (int kk = 0; kk < 2; ++kk) {
                uint32_t a[2][4];
#pragma unroll
                for (int mt = 0; mt < 2; ++mt) {
                    const int base = ((warp_m * 2 + mt) * 16 + g) * 20 + kk * 8 + t4;
                    a[mt][0] = sA[base];
                    a[mt][1] = sA[base + 8 * 20];
                    a[mt][2] = sA[base + 4];
                    a[mt][3] = sA[base + 8 * 20 + 4];
                }
#pragma unroll
                for (int nt = 0; nt < 16; ++nt) {
                    const int bi = warp_n * 1024 + ((nt * 2 + kk) * 32 + lane);
                    uint2 b = sB[bi];
#pragma unroll
                    for (int mt = 0; mt < 2; ++mt)
                        mma_f16(acc[mt][nt], a[mt], b.x, b.y);
                }
            }
        }
        cp_wait0();
        __syncthreads();
    }

    // prefetch GEMM2 B tile 0 while doing epilogue 1
    stageB(W2, 0, 0);
    cp_commit();

    // ---- epilogue 1: hidden = relu(acc + P4[recv] + Q4[send]) (b4a folded into P4) ----
    {
        uint32_t* sH = (uint32_t*)(smem + F4_SMH);
#pragma unroll
        for (int mt = 0; mt < 2; ++mt) {
#pragma unroll
            for (int rr = 0; rr < 2; ++rr) {
                const int rloc = warp_m * 32 + mt * 16 + g + rr * 8;
                int bnr, bns; edge_nodes(m0 + rloc, bnr, bns);
                const float* Pr = PQ + (size_t)bnr * 512;
                const float* Qr = PQ + (size_t)bns * 512 + 256;
#pragma unroll
                for (int nt = 0; nt < 16; ++nt) {
                    const int col = warp_n * 128 + nt * 8 + t4 * 2;
                    const float2 p = *(const float2*)(Pr + col);
                    const float2 q = *(const float2*)(Qr + col);
                    const float v0 = fmaxf(acc[mt][nt][rr * 2 + 0] + p.x + q.x, 0.f);
                    const float v1 = fmaxf(acc[mt][nt][rr * 2 + 1] + p.y + q.y, 0.f);
                    sH[rloc * 132 + warp_n * 64 + nt * 4 + t4] = pkh2(v0, v1);
                }
            }
        }
    }
#pragma unroll
    for (int i = 0; i < 2; i++)
#pragma unroll
        for (int j = 0; j < 16; j++)
#pragma unroll
            for (int c = 0; c < 4; c++) acc[i][j][c] = 0.f;

    cp_wait0();
    __syncthreads();

    // ---- GEMM2: hidden @ W2 ----
#pragma unroll 1
    for (int t2 = 0; t2 < 8; ++t2) {
        const int p = t2 & 1;
        if (t2 + 1 < 8) { stageB(W2, t2 + 1, p ^ 1); cp_commit(); }
        {
            const uint32_t* sH = (const uint32_t*)(smem + F4_SMH);
            const uint2*    sB = (const uint2*)(smem + F4_SMB(p));
#pragma unroll
            for (int kk = 0; kk < 2; ++kk) {
                uint32_t a[2][4];
#pragma unroll
                for (int mt = 0; mt < 2; ++mt) {
                    const int r0 = warp_m * 32 + mt * 16 + g;
                    const int cb = t2 * 16 + kk * 8 + t4;
                    a[mt][0] = sH[r0 * 132 + cb];
                    a[mt][1] = sH[(r0 + 8) * 132 + cb];
                    a[mt][2] = sH[r0 * 132 + cb + 4];
                    a[mt][3] = sH[(r0 + 8) * 132 + cb + 4];
                }
#pragma unroll
                for (int nt = 0; nt < 16; ++nt) {
                    const int bi = warp_n * 1024 + ((nt * 2 + kk) * 32 + lane);
                    uint2 b = sB[bi];
#pragma unroll
                    for (int mt = 0; mt < 2; ++mt)
                        mma_f16(acc[mt][nt], a[mt], b.x, b.y);
                }
            }
        }
        cp_wait0();
        __syncthreads();
    }

    // ---- epilogue 2: output head. out = (acc + b4b) @ wo + bo ----
    {
        float p[2][2][4];
#pragma unroll
        for (int mt = 0; mt < 2; ++mt)
#pragma unroll
            for (int rr = 0; rr < 2; ++rr)
#pragma unroll
                for (int j = 0; j < 4; ++j) p[mt][rr][j] = 0.f;

#pragma unroll
        for (int nt = 0; nt < 16; ++nt) {
            const int col = warp_n * 128 + nt * 8 + t4 * 2;
            const float2 bb = *(const float2*)(b2v + col);
            const float4 w0 = *(const float4*)(wo + col * 4);
            const float4 w1 = *(const float4*)(wo + (col + 1) * 4);
#pragma unroll
            for (int mt = 0; mt < 2; ++mt)
#pragma unroll
                for (int rr = 0; rr < 2; ++rr) {
                    const float v0 = acc[mt][nt][rr * 2 + 0] + bb.x;
                    const float v1 = acc[mt][nt][rr * 2 + 1] + bb.y;
                    p[mt][rr][0] += v0 * w0.x + v1 * w1.x;
                    p[mt][rr][1] += v0 * w0.y + v1 * w1.y;
                    p[mt][rr][2] += v0 * w0.z + v1 * w1.z;
                    p[mt][rr][3] += v0 * w0.w + v1 * w1.w;
                }
        }
        // reduce over t4 lanes (lane = g*4 + t4)
#pragma unroll
        for (int mt = 0; mt < 2; ++mt)
#pragma unroll
            for (int rr = 0; rr < 2; ++rr)
#pragma unroll
                for (int j = 0; j < 4; ++j) {
                    float v = p[mt][rr][j];
                    v += __shfl_xor_sync(0xffffffffu, v, 1);
                    v += __shfl_xor_sync(0xffffffffu, v, 2);
                    p[mt][rr][j] = v;
                }
        float* sO = (float*)smem;     // reuse dead A region, 4 KB
        if (t4 == 0) {
#pragma unroll
            for (int mt = 0; mt < 2; ++mt)
#pragma unroll
                for (int rr = 0; rr < 2; ++rr) {
                    const int rloc = warp_m * 32 + mt * 16 + rr * 8 + g;
#pragma unroll
                    for (int j = 0; j < 4; ++j)
                        sO[rloc * 8 + warp_n * 4 + j] = p[mt][rr][j];
                }
        }
        __syncthreads();
#pragma unroll
        for (int it = 0; it < 2; ++it) {
            const int idx = tid + it * 256;
            const int row = idx >> 2, j = idx & 3;
            out[(size_t)(m0 + row) * 4 + j] = sO[row * 8 + j] + sO[row * 8 + 4 + j] + bo[j];
        }
    }
}

// ---------------- merged weight fp16-convert + frag-order scatter (3x K=256) ----------------
__global__ void wsplit3_k(const float* __restrict__ w0, const float* __restrict__ w1s,
                          const float* __restrict__ w2s, __half* __restrict__ oh)
{
    const int grp = blockIdx.x >> 8;                 // 0,1,2
    const int lb  = blockIdx.x & 255;
    const float* w = (grp == 0) ? w0 : (grp == 1) ? w1s : w2s;
    __half* dstb = oh + (size_t)grp * 256 * 256;
    const int idx = lb * 256 + threadIdx.x;          // = k*256 + n
    const int k = idx >> 8, n = idx & 255;
    const __half hv = __float2half_rn(w[idx]);
    const int ny = n >> 7, nr = n & 127;
    const int nt = nr >> 3, gg = nr & 7;
    const int s = k >> 5, kr = k & 31;
    const int kk = kr >> 4, kr16 = kr & 15;
    const int reg = (kr16 >= 8) ? 1 : 0;
    const int t4 = (kr16 & 7) >> 1;
    const int hp = kr16 & 1;
    const int lane = gg * 4 + t4;
    const int dst = (s * 2 + ny) * 4096 + ((nt * 2 + kk) * 32 + lane) * 4 + reg * 2 + hp;
    dstb[dst] = hv;
}

// ---------------- SIMT f32x2 GEMM, 64x64 tiles, TK=16 (node layers, exact fp32) ----------------
template<int MODE, int K, int NOUT, bool RELU>
__global__ __launch_bounds__(256)
void gemm_k64(const float* __restrict__ A, const float* __restrict__ W,
              const float* __restrict__ bias, float* __restrict__ C)
{
    constexpr int TK = 16;
    __shared__ __align__(16) float sA[2][TK][68];
    __shared__ __align__(16) float sB[2][TK][64];

    const int tid = threadIdx.x;
    const int m0 = blockIdx.x * 64, n0 = blockIdx.y * 64;

    // all threads load one A float4 + one B float4 per stage
    const int a_m = tid >> 2, a_k = (tid & 3) << 2;
    const int b_k = tid >> 4, b_n = (tid & 15) << 2;

    const int m = m0 + a_m;
    const float* pr;
    if (MODE == MODE_DIR) {
        pr = A + (size_t)m * K;
    } else { // MODE_X
        int b = m / N_, n = m - b * N_;
        pr = A + (size_t)b * (T_ * N_ * D_) + (size_t)n * D_;
    }
    auto ldA = [&](int k0) -> float4 {
        const int k = k0 + a_k;
        if (MODE == MODE_DIR) return *(const float4*)(pr + k);
        return *(const float4*)(pr + (size_t)(k >> 2) * (N_ * D_));
    };
    auto ldB = [&](int k0) -> float4 {
        return *(const float4*)(W + (size_t)(k0 + b_k) * NOUT + n0 + b_n);
    };

    const int tx = tid & 15, ty = tid >> 4;
    u64 acc[4][2];
#pragma unroll
    for (int i = 0; i < 4; i++) { acc[i][0] = 0ull; acc[i][1] = 0ull; }

    constexpr int S = K / TK;    // 200/16 not integral -> handled: K=200 uses S=12 full + tail 8
    constexpr int SFULL = K / TK;
    constexpr int KTAIL = K - SFULL * TK;   // 0 or 8 (K=200 -> 12*16=192, tail 8)

    {
        float4 ra = ldA(0), rb = ldB(0);
        sA[0][a_k + 0][a_m] = ra.x; sA[0][a_k + 1][a_m] = ra.y;
        sA[0][a_k + 2][a_m] = ra.z; sA[0][a_k + 3][a_m] = ra.w;
        *(float4*)&sB[0][b_k][b_n] = rb;
    }
    __syncthreads();
    for (int s = 0; s < SFULL; ++s) {
        const int cur = s & 1;
        float4 na, nb;
        const bool more = (s + 1 < SFULL) || (KTAIL > 0 && s + 1 == SFULL);
        if (more) {
            const int kn = (s + 1) * TK;
            if (KTAIL > 0 && s + 1 == SFULL) {
                // tail stage: only first KTAIL k's valid; loaders with a_k/b_k < KTAIL
                if (a_k < KTAIL) na = ldA(kn);
                if (b_k < KTAIL) nb = ldB(kn);
            } else {
                na = ldA(kn); nb = ldB(kn);
            }
        }
#pragma unroll
        for (int k = 0; k < TK; ++k) {
            const float4 a = *(const float4*)&sA[cur][k][ty * 4];
            const ulonglong2 b = *(const ulonglong2*)&sB[cur][k][tx * 4];
            u64 ap;
            ap = pk2(a.x, a.x); fma2(acc[0][0], ap, b.x); fma2(acc[0][1], ap, b.y);
            ap = pk2(a.y, a.y); fma2(acc[1][0], ap, b.x); fma2(acc[1][1], ap, b.y);
            ap = pk2(a.z, a.z); fma2(acc[2][0], ap, b.x); fma2(acc[2][1], ap, b.y);
            ap = pk2(a.w, a.w); fma2(acc[3][0], ap, b.x); fma2(acc[3][1], ap, b.y);
        }
        if (more) {
            const int nxt = cur ^ 1;
            if (!(KTAIL > 0 && s + 1 == SFULL) || a_k < KTAIL) {
                sA[nxt][a_k + 0][a_m] = na.x; sA[nxt][a_k + 1][a_m] = na.y;
                sA[nxt][a_k + 2][a_m] = na.z; sA[nxt][a_k + 3][a_m] = na.w;
            }
            if (!(KTAIL > 0 && s + 1 == SFULL) || b_k < KTAIL)
                *(float4*)&sB[nxt][b_k][b_n] = nb;
        }
        __syncthreads();
    }
    if (KTAIL > 0) {
        const int cur = SFULL & 1;
#pragma unroll
        for (int k = 0; k < KTAIL; ++k) {
            const float4 a = *(const float4*)&sA[cur][k][ty * 4];
            const ulonglong2 b = *(const ulonglong2*)&sB[cur][k][tx * 4];
            u64 ap;
            ap = pk2(a.x, a.x); fma2(acc[0][0], ap, b.x); fma2(acc[0][1], ap, b.y);
            ap = pk2(a.y, a.y); fma2(acc[1][0], ap, b.x); fma2(acc[1][1], ap, b.y);
            ap = pk2(a.z, a.z); fma2(acc[2][0], ap, b.x); fma2(acc[2][1], ap, b.y);
            ap = pk2(a.w, a.w); fma2(acc[3][0], ap, b.x); fma2(acc[3][1], ap, b.y);
        }
        __syncthreads();
    }
    const float4 bb = *(const float4*)(bias + n0 + tx * 4);
#pragma unroll
    for (int i = 0; i < 4; ++i) {
        float v0, v1, v2, v3;
        unpk2(v0, v1, acc[i][0]);
        unpk2(v2, v3, acc[i][1]);
        v0 += bb.x; v1 += bb.y; v2 += bb.z; v3 += bb.w;
        if (RELU) {
            v0 = fmaxf(v0, 0.f); v1 = fmaxf(v1, 0.f);
            v2 = fmaxf(v2, 0.f); v3 = fmaxf(v3, 0.f);
        }
        *(float4*)(C + (size_t)(m0 + ty * 4 + i) * NOUT + n0 + tx * 4) =
            make_float4(v0, v1, v2, v3);
    }
}

// ---------------- gemm_pq64: PQ[M,512] = A[M,256] @ {W_top|W_bot}, TK=16 ----------------
__global__ __launch_bounds__(256)
void gemm_pq64(const float* __restrict__ A, const float* __restrict__ W,
               const float* __restrict__ bias, float* __restrict__ C)
{
    constexpr int K = 256, TK = 16;
    __shared__ __align__(16) float sA[2][TK][68];
    __shared__ __align__(16) float sB[2][TK][64];

    const int tid = threadIdx.x;
    const int m0 = blockIdx.x * 64;
    const int half = blockIdx.y >> 2;
    const int n0 = (blockIdx.y & 3) * 64;
    const float* Wb = W + (size_t)half * 256 * 256;

    const int a_m = tid >> 2, a_k = (tid & 3) << 2;
    const int b_k = tid >> 4, b_n = (tid & 15) << 2;
    const float* pr = A + (size_t)(m0 + a_m) * K;

    auto ldB = [&](int k0) -> float4 {
        return *(const float4*)(Wb + (size_t)(k0 + b_k) * 256 + n0 + b_n);
    };

    const int tx = tid & 15, ty = tid >> 4;
    u64 acc[4][2];
#pragma unroll
    for (int i = 0; i < 4; i++) { acc[i][0] = 0ull; acc[i][1] = 0ull; }

    {
        float4 ra = *(const float4*)(pr + a_k), rb = ldB(0);
        sA[0][a_k + 0][a_m] = ra.x; sA[0][a_k + 1][a_m] = ra.y;
        sA[0][a_k + 2][a_m] = ra.z; sA[0][a_k + 3][a_m] = ra.w;
        *(float4*)&sB[0][b_k][b_n] = rb;
    }
    __syncthreads();
    for (int s = 0; s < K / TK; ++s) {
        const int cur = s & 1;
        float4 na, nb;
        if (s + 1 < K / TK) {
            na = *(const float4*)(pr + (s + 1) * TK + a_k);
            nb = ldB((s + 1) * TK);
        }
#pragma unroll
        for (int k = 0; k < TK; ++k) {
            const float4 a = *(const float4*)&sA[cur][k][ty * 4];
            const ulonglong2 b = *(const ulonglong2*)&sB[cur][k][tx * 4];
            u64 ap;
            ap = pk2(a.x, a.x); fma2(acc[0][0], ap, b.x); fma2(acc[0][1], ap, b.y);
            ap = pk2(a.y, a.y); fma2(acc[1][0], ap, b.x); fma2(acc[1][1], ap, b.y);
            ap = pk2(a.z, a.z); fma2(acc[2][0], ap, b.x); fma2(acc[2][1], ap, b.y);
            ap = pk2(a.w, a.w); fma2(acc[3][0], ap, b.x); fma2(acc[3][1], ap, b.y);
        }
        if (s + 1 < K / TK) {
            const int nxt = cur ^ 1;
            sA[nxt][a_k + 0][a_m] = na.x; sA[nxt][a_k + 1][a_m] = na.y;
            sA[nxt][a_k + 2][a_m] = na.z; sA[nxt][a_k + 3][a_m] = na.w;
            *(float4*)&sB[nxt][b_k][b_n] = nb;
        }
        __syncthreads();
    }
    float4 bb = half ? make_float4(0.f, 0.f, 0.f, 0.f)
                     : *(const float4*)(bias + n0 + tx * 4);
#pragma unroll
    for (int i = 0; i < 4; ++i) {
        float v0, v1, v2, v3;
        unpk2(v0, v1, acc[i][0]);
        unpk2(v2, v3, acc[i][1]);
        v0 += bb.x; v1 += bb.y; v2 += bb.z; v3 += bb.w;
        *(float4*)(C + (size_t)(m0 + ty * 4 + i) * 512 + half * 256 + n0 + tx * 4) =
            make_float4(v0, v1, v2, v3);
    }
}

// ---------------- launch ----------------
extern "C" void kernel_launch(void* const* d_in, const int* in_sizes, int n_in,
                              void* d_out, int out_size)
{
    (void)in_sizes; (void)n_in; (void)out_size;
    const float* x   = (const float*)d_in[0];
    const float* w1a = (const float*)d_in[3];
    const float* b1a = (const float*)d_in[4];
    const float* w1b = (const float*)d_in[5];
    const float* b1b = (const float*)d_in[6];
    const float* w2a = (const float*)d_in[7];
    const float* b2a = (const float*)d_in[8];
    const float* w2b = (const float*)d_in[9];
    const float* b2b = (const float*)d_in[10];
    const float* w3a = (const float*)d_in[11];
    const float* b3a = (const float*)d_in[12];
    const float* w3b = (const float*)d_in[13];
    const float* b3b = (const float*)d_in[14];
    const float* w4a = (const float*)d_in[15];
    const float* b4a = (const float*)d_in[16];
    const float* w4b = (const float*)d_in[17];
    const float* b4b = (const float*)d_in[18];
    const float* wo  = (const float*)d_in[19];
    const float* bo  = (const float*)d_in[20];
    float* out = (float*)d_out;

    float *xskipf, *nodeA, *nodeB, *pq; __half* wth;
    cudaGetSymbolAddress((void**)&xskipf, g_xskip);
    cudaGetSymbolAddress((void**)&nodeA, g_nodeA);
    cudaGetSymbolAddress((void**)&nodeB, g_nodeB);
    cudaGetSymbolAddress((void**)&pq,    g_pq);
    cudaGetSymbolAddress((void**)&wth,   g_wth);
    __half* xskip16 = (__half*)xskipf;

    __half* f2b = wth;               // w2b, K=256
    __half* f4c = wth + 256 * 256;   // w4a[512:768], K=256 (x_skip block)
    __half* f4b = wth + 512 * 256;   // w4b, K=256

    cudaFuncSetAttribute(fused2, cudaFuncAttributeMaxDynamicSharedMemorySize, F2_BYTES);
    cudaFuncSetAttribute(fused4, cudaFuncAttributeMaxDynamicSharedMemorySize, F4_BYTES);

    const dim3 blk(256);
    const dim3 gN64(50, 4);
    const dim3 gPQ(50, 8);

    // Zero node accumulator first (overlaps with weight prep wave)
    zero_k<<<(B_ * N_ * H_) / 1024, 256>>>(nodeA, B_ * N_ * H_);

    // convert+scatter weights into fp16 frag-ordered layout (single launch)
    wsplit3_k<<<768, 256>>>(w2b, w4a + 512 * 256, w4b, wth);

    // MLP1 on nodes (SIMT fp32, exact): x -> relu1 (in pq tmp) -> nodeB (=h)
    gemm_k64<MODE_X,  NIN_, H_, true ><<<gN64, blk>>>(x,  w1a, b1a, pq);     // pq as tmp
    gemm_k64<MODE_DIR, H_,  H_, false><<<gN64, blk>>>(pq, w1b, b1b, nodeB);

    // Node projections for MLP2: PQ = [h@w2a_top + b2a | h@w2a_bot]
    gemm_pq64<<<gPQ, blk>>>(nodeB, w2a, b2a, pq);

    // Fused MLP2 on edges + aggregation: x_skip (fp16) and nodeA += segsum/N
    fused2<<<2475, blk, F2_BYTES>>>(pq, f2b, b2b, xskip16, nodeA);

    // MLP3 on nodes (SIMT fp32): nodeA -> nodeB(relu) -> nodeA (=v)
    gemm_k64<MODE_DIR, H_, H_, true ><<<gN64, blk>>>(nodeA, w3a, b3a, nodeB);
    gemm_k64<MODE_DIR, H_, H_, false><<<gN64, blk>>>(nodeB, w3b, b3b, nodeA);

    // Node projections for MLP4: PQ = [v@w4a_top + b4a | v@w4a_mid]
    gemm_pq64<<<gPQ, blk>>>(nodeA, w4a, b4a, pq);

    // Fused MLP4 + output head
    fused4<<<2475, blk, F4_BYTES>>>(xskip16, pq, f4c, f4b, b4b, wo, bo, out);
}

// round 16
// speedup vs baseline: 1.1348x; 1.0590x over previous
#include <cuda_runtime.h>
#include <cuda_fp16.h>
#include <cstdint>

// Problem dims
#define B_   32
#define T_   50
#define N_   100
#define D_   4
#define E_   9900          // N*(N-1)
#define BE_  316800        // B*E
#define H_   256           // hidden
#define NIN_ 200           // T*D

// Scratch (device globals; no allocation allowed)
__device__ float  g_xskip[BE_ * H_ / 2];   // __half x_skip buffer (162 MB)
__device__ float  g_nodeA[B_ * N_ * H_];   // 3.3 MB
__device__ float  g_nodeB[B_ * N_ * H_];   // 3.3 MB
__device__ float  g_pq   [B_ * N_ * 512];  // P|Q node projections, 6.6 MB
__device__ __half g_wth  [768 * 256];      // frag-ordered fp16 weights: w2b|w4c|w4b

enum { MODE_DIR = 0, MODE_X = 1 };

typedef unsigned long long u64;

// ---------------- small PTX helpers ----------------
__device__ __forceinline__ uint32_t smem_to_u32(const void* p) {
    uint32_t a;
    asm("{ .reg .u64 t; cvta.to.shared.u64 t, %1; cvt.u32.u64 %0, t; }" : "=r"(a) : "l"(p));
    return a;
}
__device__ __forceinline__ uint32_t pkh2(float x, float y) {
    __half2 h = __floats2half2_rn(x, y);
    return *(uint32_t*)&h;
}
__device__ __forceinline__ void cp16(uint32_t s, const void* g) {
    asm volatile("cp.async.cg.shared.global [%0], [%1], 16;" :: "r"(s), "l"(g) : "memory");
}
__device__ __forceinline__ void cp_commit() { asm volatile("cp.async.commit_group;" ::: "memory"); }
__device__ __forceinline__ void cp_wait0()  { asm volatile("cp.async.wait_group 0;" ::: "memory"); }

__device__ __forceinline__ void mma_f16(float* c, const uint32_t* a, uint32_t b0, uint32_t b1) {
    asm volatile(
        "mma.sync.aligned.m16n8k16.row.col.f32.f16.f16.f32 "
        "{%0,%1,%2,%3}, {%4,%5,%6,%7}, {%8,%9}, {%0,%1,%2,%3};"
        : "+f"(c[0]), "+f"(c[1]), "+f"(c[2]), "+f"(c[3])
        : "r"(a[0]), "r"(a[1]), "r"(a[2]), "r"(a[3]), "r"(b0), "r"(b1));
}

// edge index helpers
__device__ __forceinline__ void edge_nodes(int m, int& bn_rcv, int& bn_snd) {
    int b = m / E_, e = m - b * E_;
    int rcv = e / (N_ - 1), jj = e - rcv * (N_ - 1);
    int snd = jj + (jj >= rcv ? 1 : 0);
    bn_rcv = b * N_ + rcv;
    bn_snd = b * N_ + snd;
}

// SIMT f32x2 primitives
__device__ __forceinline__ u64 pk2(float lo, float hi) {
    u64 r; asm("mov.b64 %0, {%1, %2};" : "=l"(r) : "f"(lo), "f"(hi)); return r;
}
__device__ __forceinline__ void fma2(u64& d, u64 a, u64 b) {
    asm("fma.rn.f32x2 %0, %1, %2, %0;" : "+l"(d) : "l"(a), "l"(b));
}
__device__ __forceinline__ void unpk2(float& lo, float& hi, u64 v) {
    asm("mov.b64 {%0, %1}, %2;" : "=f"(lo), "=f"(hi) : "l"(v));
}

// ---------------- zero kernel for node accumulator ----------------
__global__ void zero_k(float* __restrict__ p, int n)
{
    const int i = blockIdx.x * 1024 + threadIdx.x * 4;
    if (i < n) *(float4*)(p + i) = make_float4(0.f, 0.f, 0.f, 0.f);
}

// ==================== fused2: x_skip = relu(P[recv]+Q[send]) @ W2 + b2 ====================
// Gather-add is pipelined per K-chunk with the MMA mainloop.
// Also accumulates the edge->node mean into V (nodeA) via atomics.
// 256 threads = 8 warps (4m x 2n), warp tile 32x128.
// smem: hidden chunks 2 x (128 x 20 b32) = 20480; B[2] 16 KB each @20480;
//       x_skip agg buffer 128 x 132 b32 @53248. total 120832 B.
#define F2_SMH(p) ((p) * 10240u)
#define F2_SMB(p) (20480u + (p) * 16384u)
#define F2_SMX    (53248u)
#define F2_BYTES  120832

__global__ __launch_bounds__(256, 1)
void fused2(const float* __restrict__ PQ, const __half* __restrict__ W2,
            const float* __restrict__ b2v, __half* __restrict__ C,
            float* __restrict__ V)
{
    extern __shared__ char smem[];
    const uint32_t sbase = smem_to_u32(smem);
    const int tid = threadIdx.x;
    const int m0 = blockIdx.x * 128;

    auto stageB = [&](int t, int p) {
        const char* hs = (const char*)(W2 + (size_t)t * 8192);
        const uint32_t dh = sbase + F2_SMB(p);
#pragma unroll
        for (int i = 0; i < 4; ++i) {
            const int e4 = i * 256 + tid;
            cp16(dh + e4 * 16, hs + e4 * 16);
        }
    };

    // ---- gather setup: thread handles row arow, 16-col half 'side' per chunk ----
    const int arow = tid >> 1, side = tid & 1;
    int bnr, bns; edge_nodes(m0 + arow, bnr, bns);
    const float* Pr = PQ + (size_t)bnr * 512;
    const float* Qr = PQ + (size_t)bns * 512 + 256;

    float4 gp[4], gq[4];
    auto gatherRegs = [&](int t) {
        const int c0 = t * 32 + side * 16;
#pragma unroll
        for (int j = 0; j < 4; ++j) {
            gp[j] = *(const float4*)(Pr + c0 + 4 * j);
            gq[j] = *(const float4*)(Qr + c0 + 4 * j);
        }
    };
    auto stsH = [&](int p) {
        uint32_t* dst = (uint32_t*)(smem + F2_SMH(p)) + arow * 20 + side * 8;
#pragma unroll
        for (int j = 0; j < 4; ++j) {
            const float v0 = fmaxf(gp[j].x + gq[j].x, 0.f);
            const float v1 = fmaxf(gp[j].y + gq[j].y, 0.f);
            const float v2 = fmaxf(gp[j].z + gq[j].z, 0.f);
            const float v3 = fmaxf(gp[j].w + gq[j].w, 0.f);
            dst[2 * j]     = pkh2(v0, v1);
            dst[2 * j + 1] = pkh2(v2, v3);
        }
    };

    const int wid = tid >> 5, lane = tid & 31;
    const int warp_m = wid >> 1, warp_n = wid & 1;
    const int g = lane >> 2, t4 = lane & 3;

    float acc[2][16][4];
#pragma unroll
    for (int i = 0; i < 2; i++)
#pragma unroll
        for (int j = 0; j < 16; j++)
#pragma unroll
            for (int c = 0; c < 4; c++) acc[i][j][c] = 0.f;

    // ---- prologue: hidden chunk 0 + B tile 0 ----
    stageB(0, 0);
    cp_commit();
    gatherRegs(0);
    stsH(0);
    cp_wait0();
    __syncthreads();

    // ---- pipelined mainloop over 8 K-chunks ----
#pragma unroll 1
    for (int t2 = 0; t2 < 8; ++t2) {
        const int p = t2 & 1;
        if (t2 + 1 < 8) {
            gatherRegs(t2 + 1);
            stageB(t2 + 1, p ^ 1);
            cp_commit();
        }
        {
            const uint32_t* sH = (const uint32_t*)(smem + F2_SMH(p));
            const uint2*    sB = (const uint2*)(smem + F2_SMB(p));
#pragma unroll
            for (int kk = 0; kk < 2; ++kk) {
                uint32_t a[2][4];
#pragma unroll
                for (int mt = 0; mt < 2; ++mt) {
                    const int base = ((warp_m * 2 + mt) * 16 + g) * 20 + kk * 8 + t4;
                    a[mt][0] = sH[base];
                    a[mt][1] = sH[base + 8 * 20];
                    a[mt][2] = sH[base + 4];
                    a[mt][3] = sH[base + 8 * 20 + 4];
                }
#pragma unroll
                for (int nt = 0; nt < 16; ++nt) {
                    const int bi = warp_n * 1024 + ((nt * 2 + kk) * 32 + lane);
                    uint2 b = sB[bi];
#pragma unroll
                    for (int mt = 0; mt < 2; ++mt)
                        mma_f16(acc[mt][nt], a[mt], b.x, b.y);
                }
            }
        }
        if (t2 + 1 < 8) stsH(p ^ 1);
        cp_wait0();
        __syncthreads();
    }

    // epilogue: bias, fp16 store to gmem + smem (for aggregation)
    {
        uint32_t* sX = (uint32_t*)(smem + F2_SMX);    // stride 132
#pragma unroll
        for (int mt = 0; mt < 2; ++mt) {
#pragma unroll
            for (int nt = 0; nt < 16; ++nt) {
                const int rl = warp_m * 32 + mt * 16 + g;
                const int col = warp_n * 128 + nt * 8 + t4 * 2;
                const float2 bb = *(const float2*)(b2v + col);
                const uint32_t h0 = pkh2(acc[mt][nt][0] + bb.x, acc[mt][nt][1] + bb.y);
                const uint32_t h1 = pkh2(acc[mt][nt][2] + bb.x, acc[mt][nt][3] + bb.y);
                *(uint32_t*)(C + (size_t)(m0 + rl) * 256 + col)     = h0;
                *(uint32_t*)(C + (size_t)(m0 + rl + 8) * 256 + col) = h1;
                sX[rl * 132 + (col >> 1)]       = h0;
                sX[(rl + 8) * 132 + (col >> 1)] = h1;
            }
        }
    }
    __syncthreads();

    // ---- aggregation: per node segment (bn = m/99, contiguous), sum/100, atomicAdd ----
    {
        const uint32_t* sX = (const uint32_t*)(smem + F2_SMX);
        const int cp  = tid & 127;      // column pair
        const int par = tid >> 7;       // segment parity
        const int bn0 = m0 / (N_ - 1);
        const int bn1 = (m0 + 127) / (N_ - 1);
        for (int bn = bn0 + par; bn <= bn1; bn += 2) {
            const int lo = max(bn * (N_ - 1) - m0, 0);
            const int hi = min(bn * (N_ - 1) + (N_ - 1) - m0, 128);
            float s0 = 0.f, s1 = 0.f;
            for (int r = lo; r < hi; ++r) {
                const uint32_t hv = sX[r * 132 + cp];
                __half2 h = *(const __half2*)&hv;
                float2 f = __half22float2(h);
                s0 += f.x; s1 += f.y;
            }
            atomicAdd(&V[(size_t)bn * 256 + cp * 2],     s0 * (1.0f / N_));
            atomicAdd(&V[(size_t)bn * 256 + cp * 2 + 1], s1 * (1.0f / N_));
        }
    }
}

// ==================== fused4 + output head ====================
// out[M,4] = (relu(xs@W1 + P4[recv]+Q4[send]) @ W2 + b2) @ wo + bo
#define F4_SMA(p) ((p) * 10240u)
#define F4_SMH    (20480u)
#define F4_SMB(p) (88064u + (p) * 16384u)
#define F4_BYTES  120832

__global__ __launch_bounds__(256, 1)
void fused4(const __half* __restrict__ XS, const float* __restrict__ PQ,
            const __half* __restrict__ W1, const __half* __restrict__ W2,
            const float* __restrict__ b2v, const float* __restrict__ wo,
            const float* __restrict__ bo, float* __restrict__ out)
{
    extern __shared__ char smem[];
    const uint32_t sbase = smem_to_u32(smem);
    const int tid = threadIdx.x;
    const int m0 = blockIdx.x * 128;

    const int arow = tid >> 1;
    const int kh   = (tid & 1) << 4;
    const __half* xrow = XS + (size_t)(m0 + arow) * 256;

    auto stageA = [&](int t, int p) {
        const uint32_t dst = sbase + F4_SMA(p) + (arow * 20 + (tid & 1) * 8) * 4;
        const char* src = (const char*)(xrow + t * 32 + kh);
        cp16(dst, src);
        cp16(dst + 16, src + 16);
    };
    auto stageB = [&](const __half* W, int t, int p) {
        const char* hs = (const char*)(W + (size_t)t * 8192);
        const uint32_t dh = sbase + F4_SMB(p);
#pragma unroll
        for (int i = 0; i < 4; ++i) {
            const int e4 = i * 256 + tid;
            cp16(dh + e4 * 16, hs + e4 * 16);
        }
    };

    const int wid = tid >> 5, lane = tid & 31;
    const int warp_m = wid >> 1, warp_n = wid & 1;
    const int g = lane >> 2, t4 = lane & 3;

    float acc[2][16][4];
#pragma unroll
    for (int i = 0; i < 2; i++)
#pragma unroll
        for (int j = 0; j < 16; j++)
#pragma unroll
            for (int c = 0; c < 4; c++) acc[i][j][c] = 0.f;

    // ---- GEMM1: xs[128,256] @ W1 ----
    stageA(0, 0); stageB(W1, 0, 0);
    cp_commit();
    cp_wait0();
    __syncthreads();

#pragma unroll 1
    for (int t = 0; t < 8; ++t) {
        const int p = t & 1;
        if (t + 1 < 8) { stageA(t + 1, p ^ 1); stageB(W1, t + 1, p ^ 1); cp_commit(); }
        {
            const uint32_t* sA = (const uint32_t*)(smem + F4_SMA(p));
            const uint2*    sB = (const uint2*)(smem + F4_SMB(p));
#pragma unroll
            for (int kk = 0; kk < 2; ++kk) {
                uint32_t a[2][4];
#pragma unroll
                for (int mt = 0; mt < 2; ++mt) {
                    const int base = ((warp_m * 2 + mt) * 16 + g) * 20 + kk * 8 + t4;
                    a[mt][0] = sA[base];
                    a[mt][1] = sA[base + 8 * 20];
                    a[mt][2] = sA[base + 4];
                    a[mt][3] = sA[base + 8 * 20 + 4];
                }
#pragma unroll
                for (int nt = 0; nt < 16; ++nt) {
                    const int bi = warp_n * 1024 + ((nt * 2 + kk) * 32 + lane);
                    uint2 b = sB[bi];
#pragma unroll
                    for (int mt = 0; mt < 2; ++mt)
                        mma_f16(acc[mt][nt], a[mt], b.x, b.y);
                }
            }
        }
        cp_wait0();
        __syncthreads();
    }

    // prefetch GEMM2 B tile 0 while doing epilogue 1
    stageB(W2, 0, 0);
    cp_commit();

    // ---- epilogue 1: hidden = relu(acc + P4[recv] + Q4[send]) (b4a folded into P4) ----
    {
        uint32_t* sH = (uint32_t*)(smem + F4_SMH);
#pragma unroll
        for (int mt = 0; mt < 2; ++mt) {
#pragma unroll
            for (int rr = 0; rr < 2; ++rr) {
                const int rloc = warp_m * 32 + mt * 16 + g + rr * 8;
                int bnr, bns; edge_nodes(m0 + rloc, bnr, bns);
                const float* Pr = PQ + (size_t)bnr * 512;
                const float* Qr = PQ + (size_t)bns * 512 + 256;
#pragma unroll
                for (int nt = 0; nt < 16; ++nt) {
                    const int col = warp_n * 128 + nt * 8 + t4 * 2;
                    const float2 p = *(const float2*)(Pr + col);
                    const float2 q = *(const float2*)(Qr + col);
                    const float v0 = fmaxf(acc[mt][nt][rr * 2 + 0] + p.x + q.x, 0.f);
                    const float v1 = fmaxf(acc[mt][nt][rr * 2 + 1] + p.y + q.y, 0.f);
                    sH[rloc * 132 + warp_n * 64 + nt * 4 + t4] = pkh2(v0, v1);
                }
            }
        }
    }
#pragma unroll
    for (int i = 0; i < 2; i++)
#pragma unroll
        for (int j = 0; j < 16; j++)
#pragma unroll
            for (int c = 0; c < 4; c++) acc[i][j][c] = 0.f;

    cp_wait0();
    __syncthreads();

    // ---- GEMM2: hidden @ W2 ----
#pragma unroll 1
    for (int t2 = 0; t2 < 8; ++t2) {
        const int p = t2 & 1;
        if (t2 + 1 < 8) { stageB(W2, t2 + 1, p ^ 1); cp_commit(); }
        {
            const uint32_t* sH = (const uint32_t*)(smem + F4_SMH);
            const uint2*    sB = (const uint2*)(smem + F4_SMB(p));
#pragma unroll
            for (int kk = 0; kk < 2; ++kk) {
                uint32_t a[2][4];
#pragma unroll
                for (int mt = 0; mt < 2; ++mt) {
                    const int r0 = warp_m * 32 + mt * 16 + g;
                    const int cb = t2 * 16 + kk * 8 + t4;
                    a[mt][0] = sH[r0 * 132 + cb];
                    a[mt][1] = sH[(r0 + 8) * 132 + cb];
                    a[mt][2] = sH[r0 * 132 + cb + 4];
                    a[mt][3] = sH[(r0 + 8) * 132 + cb + 4];
                }
#pragma unroll
                for (int nt = 0; nt < 16; ++nt) {
                    const int bi = warp_n * 1024 + ((nt * 2 + kk) * 32 + lane);
                    uint2 b = sB[bi];
#pragma unroll
                    for (int mt = 0; mt < 2; ++mt)
                        mma_f16(acc[mt][nt], a[mt], b.x, b.y);
                }
            }
        }
        cp_wait0();
        __syncthreads();
    }

    // ---- epilogue 2: output head. out = (acc + b4b) @ wo + bo ----
    {
        float p[2][2][4];
#pragma unroll
        for (int mt = 0; mt < 2; ++mt)
#pragma unroll
            for (int rr = 0; rr < 2; ++rr)
#pragma unroll
                for (int j = 0; j < 4; ++j) p[mt][rr][j] = 0.f;

#pragma unroll
        for (int nt = 0; nt < 16; ++nt) {
            const int col = warp_n * 128 + nt * 8 + t4 * 2;
            const float2 bb = *(const float2*)(b2v + col);
            const float4 w0 = *(const float4*)(wo + col * 4);
            const float4 w1 = *(const float4*)(wo + (col + 1) * 4);
#pragma unroll
            for (int mt = 0; mt < 2; ++mt)
#pragma unroll
                for (int rr = 0; rr < 2; ++rr) {
                    const float v0 = acc[mt][nt][rr * 2 + 0] + bb.x;
                    const float v1 = acc[mt][nt][rr * 2 + 1] + bb.y;
                    p[mt][rr][0] += v0 * w0.x + v1 * w1.x;
                    p[mt][rr][1] += v0 * w0.y + v1 * w1.y;
                    p[mt][rr][2] += v0 * w0.z + v1 * w1.z;
                    p[mt][rr][3] += v0 * w0.w + v1 * w1.w;
                }
        }
        // reduce over t4 lanes (lane = g*4 + t4)
#pragma unroll
        for (int mt = 0; mt < 2; ++mt)
#pragma unroll
            for (int rr = 0; rr < 2; ++rr)
#pragma unroll
                for (int j = 0; j < 4; ++j) {
                    float v = p[mt][rr][j];
                    v += __shfl_xor_sync(0xffffffffu, v, 1);
                    v += __shfl_xor_sync(0xffffffffu, v, 2);
                    p[mt][rr][j] = v;
                }
        float* sO = (float*)smem;     // reuse dead A region, 4 KB
        if (t4 == 0) {
#pragma unroll
            for (int mt = 0; mt < 2; ++mt)
#pragma unroll
                for (int rr = 0; rr < 2; ++rr) {
                    const int rloc = warp_m * 32 + mt * 16 + rr * 8 + g;
#pragma unroll
                    for (int j = 0; j < 4; ++j)
                        sO[rloc * 8 + warp_n * 4 + j] = p[mt][rr][j];
                }
        }
        __syncthreads();
#pragma unroll
        for (int it = 0; it < 2; ++it) {
            const int idx = tid + it * 256;
            const int row = idx >> 2, j = idx & 3;
            out[(size_t)(m0 + row) * 4 + j] = sO[row * 8 + j] + sO[row * 8 + 4 + j] + bo[j];
        }
    }
}

// ---------------- merged weight fp16-convert + frag-order scatter (3x K=256) ----------------
__global__ void wsplit3_k(const float* __restrict__ w0, const float* __restrict__ w1s,
                          const float* __restrict__ w2s, __half* __restrict__ oh)
{
    const int grp = blockIdx.x >> 8;                 // 0,1,2
    const int lb  = blockIdx.x & 255;
    const float* w = (grp == 0) ? w0 : (grp == 1) ? w1s : w2s;
    __half* dstb = oh + (size_t)grp * 256 * 256;
    const int idx = lb * 256 + threadIdx.x;          // = k*256 + n
    const int k = idx >> 8, n = idx & 255;
    const __half hv = __float2half_rn(w[idx]);
    const int ny = n >> 7, nr = n & 127;
    const int nt = nr >> 3, gg = nr & 7;
    const int s = k >> 5, kr = k & 31;
    const int kk = kr >> 4, kr16 = kr & 15;
    const int reg = (kr16 >= 8) ? 1 : 0;
    const int t4 = (kr16 & 7) >> 1;
    const int hp = kr16 & 1;
    const int lane = gg * 4 + t4;
    const int dst = (s * 2 + ny) * 4096 + ((nt * 2 + kk) * 32 + lane) * 4 + reg * 2 + hp;
    dstb[dst] = hv;
}

// ---------------- SIMT f32x2 GEMM, 64x64 tiles, TK=16 (node layers, exact fp32) ----------------
template<int MODE, int K, int NOUT, bool RELU>
__global__ __launch_bounds__(256)
void gemm_k64(const float* __restrict__ A, const float* __restrict__ W,
              const float* __restrict__ bias, float* __restrict__ C)
{
    constexpr int TK = 16;
    __shared__ __align__(16) float sA[2][TK][68];
    __shared__ __align__(16) float sB[2][TK][64];

    const int tid = threadIdx.x;
    const int m0 = blockIdx.x * 64, n0 = blockIdx.y * 64;

    const int a_m = tid >> 2, a_k = (tid & 3) << 2;
    const int b_k = tid >> 4, b_n = (tid & 15) << 2;

    const int m = m0 + a_m;
    const float* pr;
    if (MODE == MODE_DIR) {
        pr = A + (size_t)m * K;
    } else { // MODE_X
        int b = m / N_, n = m - b * N_;
        pr = A + (size_t)b * (T_ * N_ * D_) + (size_t)n * D_;
    }
    auto ldA = [&](int k0) -> float4 {
        const int k = k0 + a_k;
        if (MODE == MODE_DIR) return *(const float4*)(pr + k);
        return *(const float4*)(pr + (size_t)(k >> 2) * (N_ * D_));
    };
    auto ldB = [&](int k0) -> float4 {
        return *(const float4*)(W + (size_t)(k0 + b_k) * NOUT + n0 + b_n);
    };

    const int tx = tid & 15, ty = tid >> 4;
    u64 acc[4][2];
#pragma unroll
    for (int i = 0; i < 4; i++) { acc[i][0] = 0ull; acc[i][1] = 0ull; }

    constexpr int SFULL = K / TK;
    constexpr int KTAIL = K - SFULL * TK;   // 0 or 8 (K=200 -> tail 8)

    {
        float4 ra = ldA(0), rb = ldB(0);
        sA[0][a_k + 0][a_m] = ra.x; sA[0][a_k + 1][a_m] = ra.y;
        sA[0][a_k + 2][a_m] = ra.z; sA[0][a_k + 3][a_m] = ra.w;
        *(float4*)&sB[0][b_k][b_n] = rb;
    }
    __syncthreads();
    for (int s = 0; s < SFULL; ++s) {
        const int cur = s & 1;
        float4 na, nb;
        const bool more = (s + 1 < SFULL) || (KTAIL > 0 && s + 1 == SFULL);
        if (more) {
            const int kn = (s + 1) * TK;
            if (KTAIL > 0 && s + 1 == SFULL) {
                if (a_k < KTAIL) na = ldA(kn);
                if (b_k < KTAIL) nb = ldB(kn);
            } else {
                na = ldA(kn); nb = ldB(kn);
            }
        }
#pragma unroll
        for (int k = 0; k < TK; ++k) {
            const float4 a = *(const float4*)&sA[cur][k][ty * 4];
            const ulonglong2 b = *(const ulonglong2*)&sB[cur][k][tx * 4];
            u64 ap;
            ap = pk2(a.x, a.x); fma2(acc[0][0], ap, b.x); fma2(acc[0][1], ap, b.y);
            ap = pk2(a.y, a.y); fma2(acc[1][0], ap, b.x); fma2(acc[1][1], ap, b.y);
            ap = pk2(a.z, a.z); fma2(acc[2][0], ap, b.x); fma2(acc[2][1], ap, b.y);
            ap = pk2(a.w, a.w); fma2(acc[3][0], ap, b.x); fma2(acc[3][1], ap, b.y);
        }
        if (more) {
            const int nxt = cur ^ 1;
            if (!(KTAIL > 0 && s + 1 == SFULL) || a_k < KTAIL) {
                sA[nxt][a_k + 0][a_m] = na.x; sA[nxt][a_k + 1][a_m] = na.y;
                sA[nxt][a_k + 2][a_m] = na.z; sA[nxt][a_k + 3][a_m] = na.w;
            }
            if (!(KTAIL > 0 && s + 1 == SFULL) || b_k < KTAIL)
                *(float4*)&sB[nxt][b_k][b_n] = nb;
        }
        __syncthreads();
    }
    if (KTAIL > 0) {
        const int cur = SFULL & 1;
#pragma unroll
        for (int k = 0; k < KTAIL; ++k) {
            const float4 a = *(const float4*)&sA[cur][k][ty * 4];
            const ulonglong2 b = *(const ulonglong2*)&sB[cur][k][tx * 4];
            u64 ap;
            ap = pk2(a.x, a.x); fma2(acc[0][0], ap, b.x); fma2(acc[0][1], ap, b.y);
            ap = pk2(a.y, a.y); fma2(acc[1][0], ap, b.x); fma2(acc[1][1], ap, b.y);
            ap = pk2(a.z, a.z); fma2(acc[2][0], ap, b.x); fma2(acc[2][1], ap, b.y);
            ap = pk2(a.w, a.w); fma2(acc[3][0], ap, b.x); fma2(acc[3][1], ap, b.y);
        }
        __syncthreads();
    }
    const float4 bb = *(const float4*)(bias + n0 + tx * 4);
#pragma unroll
    for (int i = 0; i < 4; ++i) {
        float v0, v1, v2, v3;
        unpk2(v0, v1, acc[i][0]);
        unpk2(v2, v3, acc[i][1]);
        v0 += bb.x; v1 += bb.y; v2 += bb.z; v3 += bb.w;
        if (RELU) {
            v0 = fmaxf(v0, 0.f); v1 = fmaxf(v1, 0.f);
            v2 = fmaxf(v2, 0.f); v3 = fmaxf(v3, 0.f);
        }
        *(float4*)(C + (size_t)(m0 + ty * 4 + i) * NOUT + n0 + tx * 4) =
            make_float4(v0, v1, v2, v3);
    }
}

// ---------------- gemm_pq64: PQ[M,512] = A[M,256] @ {W_top|W_bot}, TK=16 ----------------
__global__ __launch_bounds__(256)
void gemm_pq64(const float* __restrict__ A, const float* __restrict__ W,
               const float* __restrict__ bias, float* __restrict__ C)
{
    constexpr int K = 256, TK = 16;
    __shared__ __align__(16) float sA[2][TK][68];
    __shared__ __align__(16) float sB[2][TK][64];

    const int tid = threadIdx.x;
    const int m0 = blockIdx.x * 64;
    const int half = blockIdx.y >> 2;
    const int n0 = (blockIdx.y & 3) * 64;
    const float* Wb = W + (size_t)half * 256 * 256;

    const int a_m = tid >> 2, a_k = (tid & 3) << 2;
    const int b_k = tid >> 4, b_n = (tid & 15) << 2;
    const float* pr = A + (size_t)(m0 + a_m) * K;

    auto ldB = [&](int k0) -> float4 {
        return *(const float4*)(Wb + (size_t)(k0 + b_k) * 256 + n0 + b_n);
    };

    const int tx = tid & 15, ty = tid >> 4;
    u64 acc[4][2];
#pragma unroll
    for (int i = 0; i < 4; i++) { acc[i][0] = 0ull; acc[i][1] = 0ull; }

    {
        float4 ra = *(const float4*)(pr + a_k), rb = ldB(0);
        sA[0][a_k + 0][a_m] = ra.x; sA[0][a_k + 1][a_m] = ra.y;
        sA[0][a_k + 2][a_m] = ra.z; sA[0][a_k + 3][a_m] = ra.w;
        *(float4*)&sB[0][b_k][b_n] = rb;
    }
    __syncthreads();
    for (int s = 0; s < K / TK; ++s) {
        const int cur = s & 1;
        float4 na, nb;
        if (s + 1 < K / TK) {
            na = *(const float4*)(pr + (s + 1) * TK + a_k);
            nb = ldB((s + 1) * TK);
        }
#pragma unroll
        for (int k = 0; k < TK; ++k) {
            const float4 a = *(const float4*)&sA[cur][k][ty * 4];
            const ulonglong2 b = *(const ulonglong2*)&sB[cur][k][tx * 4];
            u64 ap;
            ap = pk2(a.x, a.x); fma2(acc[0][0], ap, b.x); fma2(acc[0][1], ap, b.y);
            ap = pk2(a.y, a.y); fma2(acc[1][0], ap, b.x); fma2(acc[1][1], ap, b.y);
            ap = pk2(a.z, a.z); fma2(acc[2][0], ap, b.x); fma2(acc[2][1], ap, b.y);
            ap = pk2(a.w, a.w); fma2(acc[3][0], ap, b.x); fma2(acc[3][1], ap, b.y);
        }
        if (s + 1 < K / TK) {
            const int nxt = cur ^ 1;
            sA[nxt][a_k + 0][a_m] = na.x; sA[nxt][a_k + 1][a_m] = na.y;
            sA[nxt][a_k + 2][a_m] = na.z; sA[nxt][a_k + 3][a_m] = na.w;
            *(float4*)&sB[nxt][b_k][b_n] = nb;
        }
        __syncthreads();
    }
    float4 bb = half ? make_float4(0.f, 0.f, 0.f, 0.f)
                     : *(const float4*)(bias + n0 + tx * 4);
#pragma unroll
    for (int i = 0; i < 4; ++i) {
        float v0, v1, v2, v3;
        unpk2(v0, v1, acc[i][0]);
        unpk2(v2, v3, acc[i][1]);
        v0 += bb.x; v1 += bb.y; v2 += bb.z; v3 += bb.w;
        *(float4*)(C + (size_t)(m0 + ty * 4 + i) * 512 + half * 256 + n0 + tx * 4) =
            make_float4(v0, v1, v2, v3);
    }
}

// ---------------- launch ----------------
extern "C" void kernel_launch(void* const* d_in, const int* in_sizes, int n_in,
                              void* d_out, int out_size)
{
    (void)in_sizes; (void)n_in; (void)out_size;
    const float* x   = (const float*)d_in[0];
    const float* w1a = (const float*)d_in[3];
    const float* b1a = (const float*)d_in[4];
    const float* w1b = (const float*)d_in[5];
    const float* b1b = (const float*)d_in[6];
    const float* w2a = (const float*)d_in[7];
    const float* b2a = (const float*)d_in[8];
    const float* w2b = (const float*)d_in[9];
    const float* b2b = (const float*)d_in[10];
    const float* w3a = (const float*)d_in[11];
    const float* b3a = (const float*)d_in[12];
    const float* w3b = (const float*)d_in[13];
    const float* b3b = (const float*)d_in[14];
    const float* w4a = (const float*)d_in[15];
    const float* b4a = (const float*)d_in[16];
    const float* w4b = (const float*)d_in[17];
    const float* b4b = (const float*)d_in[18];
    const float* wo  = (const float*)d_in[19];
    const float* bo  = (const float*)d_in[20];
    float* out = (float*)d_out;

    float *xskipf, *nodeA, *nodeB, *pq; __half* wth;
    cudaGetSymbolAddress((void**)&xskipf, g_xskip);
    cudaGetSymbolAddress((void**)&nodeA, g_nodeA);
    cudaGetSymbolAddress((void**)&nodeB, g_nodeB);
    cudaGetSymbolAddress((void**)&pq,    g_pq);
    cudaGetSymbolAddress((void**)&wth,   g_wth);
    __half* xskip16 = (__half*)xskipf;

    __half* f2b = wth;               // w2b, K=256
    __half* f4c = wth + 256 * 256;   // w4a[512:768], K=256 (x_skip block)
    __half* f4b = wth + 512 * 256;   // w4b, K=256

    cudaFuncSetAttribute(fused2, cudaFuncAttributeMaxDynamicSharedMemorySize, F2_BYTES);
    cudaFuncSetAttribute(fused4, cudaFuncAttributeMaxDynamicSharedMemorySize, F4_BYTES);

    const dim3 blk(256);
    const dim3 gN64(50, 4);
    const dim3 gPQ(50, 8);

    // Zero node accumulator first (overlaps with weight prep wave)
    zero_k<<<(B_ * N_ * H_) / 1024, 256>>>(nodeA, B_ * N_ * H_);

    // convert+scatter weights into fp16 frag-ordered layout (single launch)
    wsplit3_k<<<768, 256>>>(w2b, w4a + 512 * 256, w4b, wth);

    // MLP1 on nodes (SIMT fp32, exact): x -> relu1 (in pq tmp) -> nodeB (=h)
    gemm_k64<MODE_X,  NIN_, H_, true ><<<gN64, blk>>>(x,  w1a, b1a, pq);     // pq as tmp
    gemm_k64<MODE_DIR, H_,  H_, false><<<gN64, blk>>>(pq, w1b, b1b, nodeB);

    // Node projections for MLP2: PQ = [h@w2a_top + b2a | h@w2a_bot]
    gemm_pq64<<<gPQ, blk>>>(nodeB, w2a, b2a, pq);

    // Fused MLP2 on edges + aggregation (pipelined gather)
    fused2<<<2475, blk, F2_BYTES>>>(pq, f2b, b2b, xskip16, nodeA);

    // MLP3 on nodes (SIMT fp32): nodeA -> nodeB(relu) -> nodeA (=v)
    gemm_k64<MODE_DIR, H_, H_, true ><<<gN64, blk>>>(nodeA, w3a, b3a, nodeB);
    gemm_k64<MODE_DIR, H_, H_, false><<<gN64, blk>>>(nodeB, w3b, b3b, nodeA);

    // Node projections for MLP4: PQ = [v@w4a_top + b4a | v@w4a_mid]
    gemm_pq64<<<gPQ, blk>>>(nodeA, w4a, b4a, pq);

    // Fused MLP4 + output head
    fused4<<<2475, blk, F4_BYTES>>>(xskip16, pq, f4c, f4b, b4b, wo, bo, out);
}

// round 17
// speedup vs baseline: 1.1418x; 1.0062x over previous
#include <cuda_runtime.h>
#include <cuda_fp16.h>
#include <cstdint>

// Problem dims
#define B_   32
#define T_   50
#define N_   100
#define D_   4
#define E_   9900          // N*(N-1)
#define BE_  316800        // B*E
#define H_   256           // hidden
#define NIN_ 200           // T*D

// Scratch (device globals; no allocation allowed)
__device__ float  g_xskip[BE_ * H_ / 2];   // __half x_skip buffer (162 MB)
__device__ float  g_nodeA[B_ * N_ * H_];   // 3.3 MB
__device__ float  g_nodeB[B_ * N_ * H_];   // 3.3 MB
__device__ float  g_pq   [B_ * N_ * 512];  // P|Q node projections, 6.6 MB
__device__ __half g_wth  [768 * 256];      // frag-ordered fp16 weights: w2b|w4c|w4b

enum { MODE_DIR = 0, MODE_X = 1 };

typedef unsigned long long u64;

// ---------------- small PTX helpers ----------------
__device__ __forceinline__ uint32_t smem_to_u32(const void* p) {
    uint32_t a;
    asm("{ .reg .u64 t; cvta.to.shared.u64 t, %1; cvt.u32.u64 %0, t; }" : "=r"(a) : "l"(p));
    return a;
}
__device__ __forceinline__ uint32_t pkh2(float x, float y) {
    __half2 h = __floats2half2_rn(x, y);
    return *(uint32_t*)&h;
}
__device__ __forceinline__ void cp16(uint32_t s, const void* g) {
    asm volatile("cp.async.cg.shared.global [%0], [%1], 16;" :: "r"(s), "l"(g) : "memory");
}
__device__ __forceinline__ void cp_commit() { asm volatile("cp.async.commit_group;" ::: "memory"); }
__device__ __forceinline__ void cp_wait0()  { asm volatile("cp.async.wait_group 0;" ::: "memory"); }

__device__ __forceinline__ void mma_f16(float* c, const uint32_t* a, uint32_t b0, uint32_t b1) {
    asm volatile(
        "mma.sync.aligned.m16n8k16.row.col.f32.f16.f16.f32 "
        "{%0,%1,%2,%3}, {%4,%5,%6,%7}, {%8,%9}, {%0,%1,%2,%3};"
        : "+f"(c[0]), "+f"(c[1]), "+f"(c[2]), "+f"(c[3])
        : "r"(a[0]), "r"(a[1]), "r"(a[2]), "r"(a[3]), "r"(b0), "r"(b1));
}

// edge index helpers
__device__ __forceinline__ void edge_nodes(int m, int& bn_rcv, int& bn_snd) {
    int b = m / E_, e = m - b * E_;
    int rcv = e / (N_ - 1), jj = e - rcv * (N_ - 1);
    int snd = jj + (jj >= rcv ? 1 : 0);
    bn_rcv = b * N_ + rcv;
    bn_snd = b * N_ + snd;
}

// SIMT f32x2 primitives
__device__ __forceinline__ u64 pk2(float lo, float hi) {
    u64 r; asm("mov.b64 %0, {%1, %2};" : "=l"(r) : "f"(lo), "f"(hi)); return r;
}
__device__ __forceinline__ void fma2(u64& d, u64 a, u64 b) {
    asm("fma.rn.f32x2 %0, %1, %2, %0;" : "+l"(d) : "l"(a), "l"(b));
}
__device__ __forceinline__ void unpk2(float& lo, float& hi, u64 v) {
    asm("mov.b64 {%0, %1}, %2;" : "=f"(lo), "=f"(hi) : "l"(v));
}

// ---------------- zero kernel for node accumulator ----------------
__global__ void zero_k(float* __restrict__ p, int n)
{
    const int i = blockIdx.x * 1024 + threadIdx.x * 4;
    if (i < n) *(float4*)(p + i) = make_float4(0.f, 0.f, 0.f, 0.f);
}

// ==================== fused2: x_skip = relu(P[recv]+Q[send]) @ W2 + b2 ====================
// Gather-add is pipelined per K-chunk with the MMA mainloop.
// Also accumulates the edge->node mean into V (nodeA) via atomics.
// 256 threads = 8 warps (4m x 2n), warp tile 32x128.
#define F2_SMH(p) ((p) * 10240u)
#define F2_SMB(p) (20480u + (p) * 16384u)
#define F2_SMX    (53248u)
#define F2_BYTES  120832

__global__ __launch_bounds__(256, 1)
void fused2(const float* __restrict__ PQ, const __half* __restrict__ W2,
            const float* __restrict__ b2v, __half* __restrict__ C,
            float* __restrict__ V)
{
    extern __shared__ char smem[];
    const uint32_t sbase = smem_to_u32(smem);
    const int tid = threadIdx.x;
    const int m0 = blockIdx.x * 128;

    auto stageB = [&](int t, int p) {
        const char* hs = (const char*)(W2 + (size_t)t * 8192);
        const uint32_t dh = sbase + F2_SMB(p);
#pragma unroll
        for (int i = 0; i < 4; ++i) {
            const int e4 = i * 256 + tid;
            cp16(dh + e4 * 16, hs + e4 * 16);
        }
    };

    // ---- gather setup: thread handles row arow, 16-col half 'side' per chunk ----
    const int arow = tid >> 1, side = tid & 1;
    int bnr, bns; edge_nodes(m0 + arow, bnr, bns);
    const float* Pr = PQ + (size_t)bnr * 512;
    const float* Qr = PQ + (size_t)bns * 512 + 256;

    float4 gp[4], gq[4];
    auto gatherRegs = [&](int t) {
        const int c0 = t * 32 + side * 16;
#pragma unroll
        for (int j = 0; j < 4; ++j) {
            gp[j] = *(const float4*)(Pr + c0 + 4 * j);
            gq[j] = *(const float4*)(Qr + c0 + 4 * j);
        }
    };
    auto stsH = [&](int p) {
        uint32_t* dst = (uint32_t*)(smem + F2_SMH(p)) + arow * 20 + side * 8;
#pragma unroll
        for (int j = 0; j < 4; ++j) {
            const float v0 = fmaxf(gp[j].x + gq[j].x, 0.f);
            const float v1 = fmaxf(gp[j].y + gq[j].y, 0.f);
            const float v2 = fmaxf(gp[j].z + gq[j].z, 0.f);
            const float v3 = fmaxf(gp[j].w + gq[j].w, 0.f);
            dst[2 * j]     = pkh2(v0, v1);
            dst[2 * j + 1] = pkh2(v2, v3);
        }
    };

    const int wid = tid >> 5, lane = tid & 31;
    const int warp_m = wid >> 1, warp_n = wid & 1;
    const int g = lane >> 2, t4 = lane & 3;

    float acc[2][16][4];
#pragma unroll
    for (int i = 0; i < 2; i++)
#pragma unroll
        for (int j = 0; j < 16; j++)
#pragma unroll
            for (int c = 0; c < 4; c++) acc[i][j][c] = 0.f;

    // ---- prologue: hidden chunk 0 + B tile 0 ----
    stageB(0, 0);
    cp_commit();
    gatherRegs(0);
    stsH(0);
    cp_wait0();
    __syncthreads();

    // ---- pipelined mainloop over 8 K-chunks ----
#pragma unroll 1
    for (int t2 = 0; t2 < 8; ++t2) {
        const int p = t2 & 1;
        if (t2 + 1 < 8) {
            gatherRegs(t2 + 1);
            stageB(t2 + 1, p ^ 1);
            cp_commit();
        }
        {
            const uint32_t* sH = (const uint32_t*)(smem + F2_SMH(p));
            const uint2*    sB = (const uint2*)(smem + F2_SMB(p));
#pragma unroll
            for (int kk = 0; kk < 2; ++kk) {
                uint32_t a[2][4];
#pragma unroll
                for (int mt = 0; mt < 2; ++mt) {
                    const int base = ((warp_m * 2 + mt) * 16 + g) * 20 + kk * 8 + t4;
                    a[mt][0] = sH[base];
                    a[mt][1] = sH[base + 8 * 20];
                    a[mt][2] = sH[base + 4];
                    a[mt][3] = sH[base + 8 * 20 + 4];
                }
#pragma unroll
                for (int nt = 0; nt < 16; ++nt) {
                    const int bi = warp_n * 1024 + ((nt * 2 + kk) * 32 + lane);
                    uint2 b = sB[bi];
#pragma unroll
                    for (int mt = 0; mt < 2; ++mt)
                        mma_f16(acc[mt][nt], a[mt], b.x, b.y);
                }
            }
        }
        if (t2 + 1 < 8) stsH(p ^ 1);
        cp_wait0();
        __syncthreads();
    }

    // epilogue: bias, fp16 store to gmem + smem (for aggregation)
    {
        uint32_t* sX = (uint32_t*)(smem + F2_SMX);    // stride 132
#pragma unroll
        for (int mt = 0; mt < 2; ++mt) {
#pragma unroll
            for (int nt = 0; nt < 16; ++nt) {
                const int rl = warp_m * 32 + mt * 16 + g;
                const int col = warp_n * 128 + nt * 8 + t4 * 2;
                const float2 bb = *(const float2*)(b2v + col);
                const uint32_t h0 = pkh2(acc[mt][nt][0] + bb.x, acc[mt][nt][1] + bb.y);
                const uint32_t h1 = pkh2(acc[mt][nt][2] + bb.x, acc[mt][nt][3] + bb.y);
                *(uint32_t*)(C + (size_t)(m0 + rl) * 256 + col)     = h0;
                *(uint32_t*)(C + (size_t)(m0 + rl + 8) * 256 + col) = h1;
                sX[rl * 132 + (col >> 1)]       = h0;
                sX[(rl + 8) * 132 + (col >> 1)] = h1;
            }
        }
    }
    __syncthreads();

    // ---- aggregation: per node segment (bn = m/99, contiguous), sum/100, atomicAdd ----
    {
        const uint32_t* sX = (const uint32_t*)(smem + F2_SMX);
        const int cp  = tid & 127;      // column pair
        const int par = tid >> 7;       // segment parity
        const int bn0 = m0 / (N_ - 1);
        const int bn1 = (m0 + 127) / (N_ - 1);
        for (int bn = bn0 + par; bn <= bn1; bn += 2) {
            const int lo = max(bn * (N_ - 1) - m0, 0);
            const int hi = min(bn * (N_ - 1) + (N_ - 1) - m0, 128);
            float s0 = 0.f, s1 = 0.f;
            for (int r = lo; r < hi; ++r) {
                const uint32_t hv = sX[r * 132 + cp];
                __half2 h = *(const __half2*)&hv;
                float2 f = __half22float2(h);
                s0 += f.x; s1 += f.y;
            }
            atomicAdd(&V[(size_t)bn * 256 + cp * 2],     s0 * (1.0f / N_));
            atomicAdd(&V[(size_t)bn * 256 + cp * 2 + 1], s1 * (1.0f / N_));
        }
    }
}

// ==================== fused4 + output head (pipelined P/Q prefetch) ====================
// out[M,4] = (relu(xs@W1 + P4[recv]+Q4[send]) @ W2 + b2) @ wo + bo
// S = P+Q (fp16) staged into sH during GEMM1; epilogue-1 is pure smem RMW.
#define F4_SMA(p) ((p) * 10240u)
#define F4_SMH    (20480u)
#define F4_SMB(p) (88064u + (p) * 16384u)
#define F4_BYTES  120832

__global__ __launch_bounds__(256, 1)
void fused4(const __half* __restrict__ XS, const float* __restrict__ PQ,
            const __half* __restrict__ W1, const __half* __restrict__ W2,
            const float* __restrict__ b2v, const float* __restrict__ wo,
            const float* __restrict__ bo, float* __restrict__ out)
{
    extern __shared__ char smem[];
    const uint32_t sbase = smem_to_u32(smem);
    const int tid = threadIdx.x;
    const int m0 = blockIdx.x * 128;

    const int arow = tid >> 1, side = tid & 1;
    const int kh   = side << 4;
    const __half* xrow = XS + (size_t)(m0 + arow) * 256;

    // P/Q gather setup (same row/side mapping as fused2)
    int bnr, bns; edge_nodes(m0 + arow, bnr, bns);
    const float* Pr = PQ + (size_t)bnr * 512;
    const float* Qr = PQ + (size_t)bns * 512 + 256;
    float4 gp[4], gq[4];
    auto gatherRegs = [&](int t) {
        const int c0 = t * 32 + side * 16;
#pragma unroll
        for (int j = 0; j < 4; ++j) {
            gp[j] = *(const float4*)(Pr + c0 + 4 * j);
            gq[j] = *(const float4*)(Qr + c0 + 4 * j);
        }
    };
    // store S = P+Q (fp16) into sH at its final column positions (stride 132)
    auto stsS = [&](int t) {
        uint32_t* dst = (uint32_t*)(smem + F4_SMH) + arow * 132 + ((t * 32 + side * 16) >> 1);
#pragma unroll
        for (int j = 0; j < 4; ++j) {
            dst[2 * j]     = pkh2(gp[j].x + gq[j].x, gp[j].y + gq[j].y);
            dst[2 * j + 1] = pkh2(gp[j].z + gq[j].z, gp[j].w + gq[j].w);
        }
    };

    auto stageA = [&](int t, int p) {
        const uint32_t dst = sbase + F4_SMA(p) + (arow * 20 + side * 8) * 4;
        const char* src = (const char*)(xrow + t * 32 + kh);
        cp16(dst, src);
        cp16(dst + 16, src + 16);
    };
    auto stageB = [&](const __half* W, int t, int p) {
        const char* hs = (const char*)(W + (size_t)t * 8192);
        const uint32_t dh = sbase + F4_SMB(p);
#pragma unroll
        for (int i = 0; i < 4; ++i) {
            const int e4 = i * 256 + tid;
            cp16(dh + e4 * 16, hs + e4 * 16);
        }
    };

    const int wid = tid >> 5, lane = tid & 31;
    const int warp_m = wid >> 1, warp_n = wid & 1;
    const int g = lane >> 2, t4 = lane & 3;

    float acc[2][16][4];
#pragma unroll
    for (int i = 0; i < 2; i++)
#pragma unroll
        for (int j = 0; j < 16; j++)
#pragma unroll
            for (int c = 0; c < 4; c++) acc[i][j][c] = 0.f;

    // ---- GEMM1: xs[128,256] @ W1, with pipelined S-prefetch into sH ----
    stageA(0, 0); stageB(W1, 0, 0);
    cp_commit();
    gatherRegs(0);
    stsS(0);
    cp_wait0();
    __syncthreads();

#pragma unroll 1
    for (int t = 0; t < 8; ++t) {
        const int p = t & 1;
        if (t + 1 < 8) {
            stageA(t + 1, p ^ 1); stageB(W1, t + 1, p ^ 1); cp_commit();
            gatherRegs(t + 1);
        }
        {
            const uint32_t* sA = (const uint32_t*)(smem + F4_SMA(p));
            const uint2*    sB = (const uint2*)(smem + F4_SMB(p));
#pragma unroll
            for (int kk = 0; kk < 2; ++kk) {
                uint32_t a[2][4];
#pragma unroll
                for (int mt = 0; mt < 2; ++mt) {
                    const int base = ((warp_m * 2 + mt) * 16 + g) * 20 + kk * 8 + t4;
                    a[mt][0] = sA[base];
                    a[mt][1] = sA[base + 8 * 20];
                    a[mt][2] = sA[base + 4];
                    a[mt][3] = sA[base + 8 * 20 + 4];
                }
#pragma unroll
                for (int nt = 0; nt < 16; ++nt) {
                    const int bi = warp_n * 1024 + ((nt * 2 + kk) * 32 + lane);
                    uint2 b = sB[bi];
#pragma unroll
                    for (int mt = 0; mt < 2; ++mt)
                        mma_f16(acc[mt][nt], a[mt], b.x, b.y);
                }
            }
        }
        if (t + 1 < 8) stsS(t + 1);
        cp_wait0();
        __syncthreads();
    }

    // prefetch GEMM2 B tile 0 while doing epilogue 1
    stageB(W2, 0, 0);
    cp_commit();

    // ---- epilogue 1: hidden = relu(acc + S) — pure smem RMW (S already in sH) ----
    {
        uint32_t* sH = (uint32_t*)(smem + F4_SMH);
#pragma unroll
        for (int mt = 0; mt < 2; ++mt) {
#pragma unroll
            for (int rr = 0; rr < 2; ++rr) {
                const int rloc = warp_m * 32 + mt * 16 + g + rr * 8;
#pragma unroll
                for (int nt = 0; nt < 16; ++nt) {
                    const int pos = rloc * 132 + warp_n * 64 + nt * 4 + t4;
                    const uint32_t sv = sH[pos];
                    const float2 s = __half22float2(*(const __half2*)&sv);
                    const float v0 = fmaxf(acc[mt][nt][rr * 2 + 0] + s.x, 0.f);
                    const float v1 = fmaxf(acc[mt][nt][rr * 2 + 1] + s.y, 0.f);
                    sH[pos] = pkh2(v0, v1);
                }
            }
        }
    }
#pragma unroll
    for (int i = 0; i < 2; i++)
#pragma unroll
        for (int j = 0; j < 16; j++)
#pragma unroll
            for (int c = 0; c < 4; c++) acc[i][j][c] = 0.f;

    cp_wait0();
    __syncthreads();

    // ---- GEMM2: hidden @ W2 ----
#pragma unroll 1
    for (int t2 = 0; t2 < 8; ++t2) {
        const int p = t2 & 1;
        if (t2 + 1 < 8) { stageB(W2, t2 + 1, p ^ 1); cp_commit(); }
        {
            const uint32_t* sH = (const uint32_t*)(smem + F4_SMH);
            const uint2*    sB = (const uint2*)(smem + F4_SMB(p));
#pragma unroll
            for (int kk = 0; kk < 2; ++kk) {
                uint32_t a[2][4];
#pragma unroll
                for (int mt = 0; mt < 2; ++mt) {
                    const int r0 = warp_m * 32 + mt * 16 + g;
                    const int cb = t2 * 16 + kk * 8 + t4;
                    a[mt][0] = sH[r0 * 132 + cb];
                    a[mt][1] = sH[(r0 + 8) * 132 + cb];
                    a[mt][2] = sH[r0 * 132 + cb + 4];
                    a[mt][3] = sH[(r0 + 8) * 132 + cb + 4];
                }
#pragma unroll
                for (int nt = 0; nt < 16; ++nt) {
                    const int bi = warp_n * 1024 + ((nt * 2 + kk) * 32 + lane);
                    uint2 b = sB[bi];
#pragma unroll
                    for (int mt = 0; mt < 2; ++mt)
                        mma_f16(acc[mt][nt], a[mt], b.x, b.y);
                }
            }
        }
        cp_wait0();
        __syncthreads();
    }

    // ---- epilogue 2: output head. out = (acc + b4b) @ wo + bo ----
    {
        float p[2][2][4];
#pragma unroll
        for (int mt = 0; mt < 2; ++mt)
#pragma unroll
            for (int rr = 0; rr < 2; ++rr)
#pragma unroll
                for (int j = 0; j < 4; ++j) p[mt][rr][j] = 0.f;

#pragma unroll
        for (int nt = 0; nt < 16; ++nt) {
            const int col = warp_n * 128 + nt * 8 + t4 * 2;
            const float2 bb = *(const float2*)(b2v + col);
            const float4 w0 = *(const float4*)(wo + col * 4);
            const float4 w1 = *(const float4*)(wo + (col + 1) * 4);
#pragma unroll
            for (int mt = 0; mt < 2; ++mt)
#pragma unroll
                for (int rr = 0; rr < 2; ++rr) {
                    const float v0 = acc[mt][nt][rr * 2 + 0] + bb.x;
                    const float v1 = acc[mt][nt][rr * 2 + 1] + bb.y;
                    p[mt][rr][0] += v0 * w0.x + v1 * w1.x;
                    p[mt][rr][1] += v0 * w0.y + v1 * w1.y;
                    p[mt][rr][2] += v0 * w0.z + v1 * w1.z;
                    p[mt][rr][3] += v0 * w0.w + v1 * w1.w;
                }
        }
        // reduce over t4 lanes (lane = g*4 + t4)
#pragma unroll
        for (int mt = 0; mt < 2; ++mt)
#pragma unroll
            for (int rr = 0; rr < 2; ++rr)
#pragma unroll
                for (int j = 0; j < 4; ++j) {
                    float v = p[mt][rr][j];
                    v += __shfl_xor_sync(0xffffffffu, v, 1);
                    v += __shfl_xor_sync(0xffffffffu, v, 2);
                    p[mt][rr][j] = v;
                }
        float* sO = (float*)smem;     // reuse dead A region, 4 KB
        if (t4 == 0) {
#pragma unroll
            for (int mt = 0; mt < 2; ++mt)
#pragma unroll
                for (int rr = 0; rr < 2; ++rr) {
                    const int rloc = warp_m * 32 + mt * 16 + rr * 8 + g;
#pragma unroll
                    for (int j = 0; j < 4; ++j)
                        sO[rloc * 8 + warp_n * 4 + j] = p[mt][rr][j];
                }
        }
        __syncthreads();
#pragma unroll
        for (int it = 0; it < 2; ++it) {
            const int idx = tid + it * 256;
            const int row = idx >> 2, j = idx & 3;
            out[(size_t)(m0 + row) * 4 + j] = sO[row * 8 + j] + sO[row * 8 + 4 + j] + bo[j];
        }
    }
}

// ---------------- merged weight fp16-convert + frag-order scatter (3x K=256) ----------------
__global__ void wsplit3_k(const float* __restrict__ w0, const float* __restrict__ w1s,
                          const float* __restrict__ w2s, __half* __restrict__ oh)
{
    const int grp = blockIdx.x >> 8;                 // 0,1,2
    const int lb  = blockIdx.x & 255;
    const float* w = (grp == 0) ? w0 : (grp == 1) ? w1s : w2s;
    __half* dstb = oh + (size_t)grp * 256 * 256;
    const int idx = lb * 256 + threadIdx.x;          // = k*256 + n
    const int k = idx >> 8, n = idx & 255;
    const __half hv = __float2half_rn(w[idx]);
    const int ny = n >> 7, nr = n & 127;
    const int nt = nr >> 3, gg = nr & 7;
    const int s = k >> 5, kr = k & 31;
    const int kk = kr >> 4, kr16 = kr & 15;
    const int reg = (kr16 >= 8) ? 1 : 0;
    const int t4 = (kr16 & 7) >> 1;
    const int hp = kr16 & 1;
    const int lane = gg * 4 + t4;
    const int dst = (s * 2 + ny) * 4096 + ((nt * 2 + kk) * 32 + lane) * 4 + reg * 2 + hp;
    dstb[dst] = hv;
}

// ---------------- SIMT f32x2 GEMM, 64x64 tiles, TK=16 (node layers, exact fp32) ----------------
template<int MODE, int K, int NOUT, bool RELU>
__global__ __launch_bounds__(256)
void gemm_k64(const float* __restrict__ A, const float* __restrict__ W,
              const float* __restrict__ bias, float* __restrict__ C)
{
    constexpr int TK = 16;
    __shared__ __align__(16) float sA[2][TK][68];
    __shared__ __align__(16) float sB[2][TK][64];

    const int tid = threadIdx.x;
    const int m0 = blockIdx.x * 64, n0 = blockIdx.y * 64;

    const int a_m = tid >> 2, a_k = (tid & 3) << 2;
    const int b_k = tid >> 4, b_n = (tid & 15) << 2;

    const int m = m0 + a_m;
    const float* pr;
    if (MODE == MODE_DIR) {
        pr = A + (size_t)m * K;
    } else { // MODE_X
        int b = m / N_, n = m - b * N_;
        pr = A + (size_t)b * (T_ * N_ * D_) + (size_t)n * D_;
    }
    auto ldA = [&](int k0) -> float4 {
        const int k = k0 + a_k;
        if (MODE == MODE_DIR) return *(const float4*)(pr + k);
        return *(const float4*)(pr + (size_t)(k >> 2) * (N_ * D_));
    };
    auto ldB = [&](int k0) -> float4 {
        return *(const float4*)(W + (size_t)(k0 + b_k) * NOUT + n0 + b_n);
    };

    const int tx = tid & 15, ty = tid >> 4;
    u64 acc[4][2];
#pragma unroll
    for (int i = 0; i < 4; i++) { acc[i][0] = 0ull; acc[i][1] = 0ull; }

    constexpr int SFULL = K / TK;
    constexpr int KTAIL = K - SFULL * TK;   // 0 or 8 (K=200 -> tail 8)

    {
        float4 ra = ldA(0), rb = ldB(0);
        sA[0][a_k + 0][a_m] = ra.x; sA[0][a_k + 1][a_m] = ra.y;
        sA[0][a_k + 2][a_m] = ra.z; sA[0][a_k + 3][a_m] = ra.w;
        *(float4*)&sB[0][b_k][b_n] = rb;
    }
    __syncthreads();
    for (int s = 0; s < SFULL; ++s) {
        const int cur = s & 1;
        float4 na, nb;
        const bool more = (s + 1 < SFULL) || (KTAIL > 0 && s + 1 == SFULL);
        if (more) {
            const int kn = (s + 1) * TK;
            if (KTAIL > 0 && s + 1 == SFULL) {
                if (a_k < KTAIL) na = ldA(kn);
                if (b_k < KTAIL) nb = ldB(kn);
            } else {
                na = ldA(kn); nb = ldB(kn);
            }
        }
#pragma unroll
        for (int k = 0; k < TK; ++k) {
            const float4 a = *(const float4*)&sA[cur][k][ty * 4];
            const ulonglong2 b = *(const ulonglong2*)&sB[cur][k][tx * 4];
            u64 ap;
            ap = pk2(a.x, a.x); fma2(acc[0][0], ap, b.x); fma2(acc[0][1], ap, b.y);
            ap = pk2(a.y, a.y); fma2(acc[1][0], ap, b.x); fma2(acc[1][1], ap, b.y);
            ap = pk2(a.z, a.z); fma2(acc[2][0], ap, b.x); fma2(acc[2][1], ap, b.y);
            ap = pk2(a.w, a.w); fma2(acc[3][0], ap, b.x); fma2(acc[3][1], ap, b.y);
        }
        if (more) {
            const int nxt = cur ^ 1;
            if (!(KTAIL > 0 && s + 1 == SFULL) || a_k < KTAIL) {
                sA[nxt][a_k + 0][a_m] = na.x; sA[nxt][a_k + 1][a_m] = na.y;
                sA[nxt][a_k + 2][a_m] = na.z; sA[nxt][a_k + 3][a_m] = na.w;
            }
            if (!(KTAIL > 0 && s + 1 == SFULL) || b_k < KTAIL)
                *(float4*)&sB[nxt][b_k][b_n] = nb;
        }
        __syncthreads();
    }
    if (KTAIL > 0) {
        const int cur = SFULL & 1;
#pragma unroll
        for (int k = 0; k < KTAIL; ++k) {
            const float4 a = *(const float4*)&sA[cur][k][ty * 4];
            const ulonglong2 b = *(const ulonglong2*)&sB[cur][k][tx * 4];
            u64 ap;
            ap = pk2(a.x, a.x); fma2(acc[0][0], ap, b.x); fma2(acc[0][1], ap, b.y);
            ap = pk2(a.y, a.y); fma2(acc[1][0], ap, b.x); fma2(acc[1][1], ap, b.y);
            ap = pk2(a.z, a.z); fma2(acc[2][0], ap, b.x); fma2(acc[2][1], ap, b.y);
            ap = pk2(a.w, a.w); fma2(acc[3][0], ap, b.x); fma2(acc[3][1], ap, b.y);
        }
        __syncthreads();
    }
    const float4 bb = *(const float4*)(bias + n0 + tx * 4);
#pragma unroll
    for (int i = 0; i < 4; ++i) {
        float v0, v1, v2, v3;
        unpk2(v0, v1, acc[i][0]);
        unpk2(v2, v3, acc[i][1]);
        v0 += bb.x; v1 += bb.y; v2 += bb.z; v3 += bb.w;
        if (RELU) {
            v0 = fmaxf(v0, 0.f); v1 = fmaxf(v1, 0.f);
            v2 = fmaxf(v2, 0.f); v3 = fmaxf(v3, 0.f);
        }
        *(float4*)(C + (size_t)(m0 + ty * 4 + i) * NOUT + n0 + tx * 4) =
            make_float4(v0, v1, v2, v3);
    }
}

// ---------------- gemm_pq64: PQ[M,512] = A[M,256] @ {W_top|W_bot}, TK=16 ----------------
__global__ __launch_bounds__(256)
void gemm_pq64(const float* __restrict__ A, const float* __restrict__ W,
               const float* __restrict__ bias, float* __restrict__ C)
{
    constexpr int K = 256, TK = 16;
    __shared__ __align__(16) float sA[2][TK][68];
    __shared__ __align__(16) float sB[2][TK][64];

    const int tid = threadIdx.x;
    const int m0 = blockIdx.x * 64;
    const int half = blockIdx.y >> 2;
    const int n0 = (blockIdx.y & 3) * 64;
    const float* Wb = W + (size_t)half * 256 * 256;

    const int a_m = tid >> 2, a_k = (tid & 3) << 2;
    const int b_k = tid >> 4, b_n = (tid & 15) << 2;
    const float* pr = A + (size_t)(m0 + a_m) * K;

    auto ldB = [&](int k0) -> float4 {
        return *(const float4*)(Wb + (size_t)(k0 + b_k) * 256 + n0 + b_n);
    };

    const int tx = tid & 15, ty = tid >> 4;
    u64 acc[4][2];
#pragma unroll
    for (int i = 0; i < 4; i++) { acc[i][0] = 0ull; acc[i][1] = 0ull; }

    {
        float4 ra = *(const float4*)(pr + a_k), rb = ldB(0);
        sA[0][a_k + 0][a_m] = ra.x; sA[0][a_k + 1][a_m] = ra.y;
        sA[0][a_k + 2][a_m] = ra.z; sA[0][a_k + 3][a_m] = ra.w;
        *(float4*)&sB[0][b_k][b_n] = rb;
    }
    __syncthreads();
    for (int s = 0; s < K / TK; ++s) {
        const int cur = s & 1;
        float4 na, nb;
        if (s + 1 < K / TK) {
            na = *(const float4*)(pr + (s + 1) * TK + a_k);
            nb = ldB((s + 1) * TK);
        }
#pragma unroll
        for (int k = 0; k < TK; ++k) {
            const float4 a = *(const float4*)&sA[cur][k][ty * 4];
            const ulonglong2 b = *(const ulonglong2*)&sB[cur][k][tx * 4];
            u64 ap;
            ap = pk2(a.x, a.x); fma2(acc[0][0], ap, b.x); fma2(acc[0][1], ap, b.y);
            ap = pk2(a.y, a.y); fma2(acc[1][0], ap, b.x); fma2(acc[1][1], ap, b.y);
            ap = pk2(a.z, a.z); fma2(acc[2][0], ap, b.x); fma2(acc[2][1], ap, b.y);
            ap = pk2(a.w, a.w); fma2(acc[3][0], ap, b.x); fma2(acc[3][1], ap, b.y);
        }
        if (s + 1 < K / TK) {
            const int nxt = cur ^ 1;
            sA[nxt][a_k + 0][a_m] = na.x; sA[nxt][a_k + 1][a_m] = na.y;
            sA[nxt][a_k + 2][a_m] = na.z; sA[nxt][a_k + 3][a_m] = na.w;
            *(float4*)&sB[nxt][b_k][b_n] = nb;
        }
        __syncthreads();
    }
    float4 bb = half ? make_float4(0.f, 0.f, 0.f, 0.f)
                     : *(const float4*)(bias + n0 + tx * 4);
#pragma unroll
    for (int i = 0; i < 4; ++i) {
        float v0, v1, v2, v3;
        unpk2(v0, v1, acc[i][0]);
        unpk2(v2, v3, acc[i][1]);
        v0 += bb.x; v1 += bb.y; v2 += bb.z; v3 += bb.w;
        *(float4*)(C + (size_t)(m0 + ty * 4 + i) * 512 + half * 256 + n0 + tx * 4) =
            make_float4(v0, v1, v2, v3);
    }
}

// ---------------- launch ----------------
extern "C" void kernel_launch(void* const* d_in, const int* in_sizes, int n_in,
                              void* d_out, int out_size)
{
    (void)in_sizes; (void)n_in; (void)out_size;
    const float* x   = (const float*)d_in[0];
    const float* w1a = (const float*)d_in[3];
    const float* b1a = (const float*)d_in[4];
    const float* w1b = (const float*)d_in[5];
    const float* b1b = (const float*)d_in[6];
    const float* w2a = (const float*)d_in[7];
    const float* b2a = (const float*)d_in[8];
    const float* w2b = (const float*)d_in[9];
    const float* b2b = (const float*)d_in[10];
    const float* w3a = (const float*)d_in[11];
    const float* b3a = (const float*)d_in[12];
    const float* w3b = (const float*)d_in[13];
    const float* b3b = (const float*)d_in[14];
    const float* w4a = (const float*)d_in[15];
    const float* b4a = (const float*)d_in[16];
    const float* w4b = (const float*)d_in[17];
    const float* b4b = (const float*)d_in[18];
    const float* wo  = (const float*)d_in[19];
    const float* bo  = (const float*)d_in[20];
    float* out = (float*)d_out;

    float *xskipf, *nodeA, *nodeB, *pq; __half* wth;
    cudaGetSymbolAddress((void**)&xskipf, g_xskip);
    cudaGetSymbolAddress((void**)&nodeA, g_nodeA);
    cudaGetSymbolAddress((void**)&nodeB, g_nodeB);
    cudaGetSymbolAddress((void**)&pq,    g_pq);
    cudaGetSymbolAddress((void**)&wth,   g_wth);
    __half* xskip16 = (__half*)xskipf;

    __half* f2b = wth;               // w2b, K=256
    __half* f4c = wth + 256 * 256;   // w4a[512:768], K=256 (x_skip block)
    __half* f4b = wth + 512 * 256;   // w4b, K=256

    cudaFuncSetAttribute(fused2, cudaFuncAttributeMaxDynamicSharedMemorySize, F2_BYTES);
    cudaFuncSetAttribute(fused4, cudaFuncAttributeMaxDynamicSharedMemorySize, F4_BYTES);

    const dim3 blk(256);
    const dim3 gN64(50, 4);
    const dim3 gPQ(50, 8);

    // Zero node accumulator first (overlaps with weight prep wave)
    zero_k<<<(B_ * N_ * H_) / 1024, 256>>>(nodeA, B_ * N_ * H_);

    // convert+scatter weights into fp16 frag-ordered layout (single launch)
    wsplit3_k<<<768, 256>>>(w2b, w4a + 512 * 256, w4b, wth);

    // MLP1 on nodes (SIMT fp32, exact): x -> relu1 (in pq tmp) -> nodeB (=h)
    gemm_k64<MODE_X,  NIN_, H_, true ><<<gN64, blk>>>(x,  w1a, b1a, pq);     // pq as tmp
    gemm_k64<MODE_DIR, H_,  H_, false><<<gN64, blk>>>(pq, w1b, b1b, nodeB);

    // Node projections for MLP2: PQ = [h@w2a_top + b2a | h@w2a_bot]
    gemm_pq64<<<gPQ, blk>>>(nodeB, w2a, b2a, pq);

    // Fused MLP2 on edges + aggregation (pipelined gather)
    fused2<<<2475, blk, F2_BYTES>>>(pq, f2b, b2b, xskip16, nodeA);

    // MLP3 on nodes (SIMT fp32): nodeA -> nodeB(relu) -> nodeA (=v)
    gemm_k64<MODE_DIR, H_, H_, true ><<<gN64, blk>>>(nodeA, w3a, b3a, nodeB);
    gemm_k64<MODE_DIR, H_, H_, false><<<gN64, blk>>>(nodeB, w3b, b3b, nodeA);

    // Node projections for MLP4: PQ = [v@w4a_top + b4a | v@w4a_mid]
    gemm_pq64<<<gPQ, blk>>>(nodeA, w4a, b4a, pq);

    // Fused MLP4 + output head (pipelined S-prefetch)
    fused4<<<2475, blk, F4_BYTES>>>(xskip16, pq, f4c, f4b, b4b, wo, bo, out);
}